// round 4
// baseline (speedup 1.0000x reference)
#include <cuda_runtime.h>
#include <math.h>
#include <stdint.h>

#define B_SZ    4
#define LSEQ    2048
#define D_MODEL 1024
#define D_INNER 2048
#define D_HALF  1024
#define D_STATE 16
#define DT_RANK 64
#define ROWS    (B_SZ * LSEQ)   /* 8192 */
#define XDBL_W  96              /* DT_RANK + 2*D_STATE */

/* ------------------------------------------------------------------ */
/* Scratch (allocation-free rule: __device__ globals)                  */
/* ------------------------------------------------------------------ */
__device__ float g_xz   [ROWS * D_INNER];     /* 64 MB */
__device__ float g_u    [ROWS * D_HALF];      /* 32 MB  xs after conv+silu */
__device__ float g_xdbl [ROWS * XDBL_W];      /*  3 MB  [dt_low | B | C]   */
__device__ float g_delta[ROWS * D_HALF];      /* 32 MB */
__device__ float g_cat  [ROWS * D_INNER];     /* 64 MB  [y | z]            */
__device__ float g_bt   [D_INNER * D_MODEL];  /*  8 MB  transposed weights */

__device__ __forceinline__ uint32_t f2tf(float x) {
    uint32_t r;
    asm("cvt.rna.tf32.f32 %0, %1;" : "=r"(r) : "f"(x));
    return r;
}

__device__ __forceinline__ uint32_t smem_u32(const void* p) {
    return (uint32_t)__cvta_generic_to_shared(p);
}

#define LDSM4(r, addr)                                                     \
    asm volatile("ldmatrix.sync.aligned.m8n8.x4.shared.b16 "               \
                 "{%0,%1,%2,%3}, [%4];"                                    \
                 : "=r"((r)[0]), "=r"((r)[1]), "=r"((r)[2]), "=r"((r)[3])  \
                 : "r"(addr))

__device__ __forceinline__ void mma_tf32(float* c, const uint32_t* a, const uint32_t* b) {
    asm volatile(
        "mma.sync.aligned.m16n8k8.row.col.f32.tf32.tf32.f32 "
        "{%0,%1,%2,%3}, {%4,%5,%6,%7}, {%8,%9}, {%0,%1,%2,%3};"
        : "+f"(c[0]), "+f"(c[1]), "+f"(c[2]), "+f"(c[3])
        : "r"(a[0]), "r"(a[1]), "r"(a[2]), "r"(a[3]), "r"(b[0]), "r"(b[1]));
}

/* ------------------------------------------------------------------ */
/* Weight transpose + tf32 round: out[C][R] = tf32(in[R][C])           */
/* ------------------------------------------------------------------ */
__global__ void transpose_tf32_kernel(const float* __restrict__ in,
                                      float* __restrict__ out, int R, int C)
{
    __shared__ float t[32][33];
    int c0 = blockIdx.x * 32, r0 = blockIdx.y * 32;
#pragma unroll
    for (int j = 0; j < 32; j += 8) {
        int r = r0 + threadIdx.y + j, c = c0 + threadIdx.x;
        if (r < R && c < C) t[threadIdx.y + j][threadIdx.x] = in[(size_t)r * C + c];
    }
    __syncthreads();
#pragma unroll
    for (int j = 0; j < 32; j += 8) {
        int c = c0 + threadIdx.y + j, r = r0 + threadIdx.x;
        if (c < C && r < R)
            out[(size_t)c * R + r] = __uint_as_float(f2tf(t[threadIdx.x][threadIdx.y + j]));
    }
}

/* ------------------------------------------------------------------ */
/* TF32 tensor-core GEMM: C = A(MxK) @ B(KxN), A row-major [M][K],     */
/* B given PRE-TRANSPOSED + tf32-rounded as Bt[N][K] (ld = K).         */
/* mode 0: plain; 1: softplus(v + 2*bias[col]); 2: v + bias[col].     */
/* CTA 128x128x16 double-buffered, 8 warps, warp 32x64, ldmatrix.      */
/* Req: M%128==0, K%16==0, lda%4==0.                                   */
/* ------------------------------------------------------------------ */
#define BM 128
#define BN 128
#define BK 16
#define SROW 20                 /* smem row stride in floats */
#define STAGE_B (BM * SROW * 4) /* stage stride in bytes = 10240 */

__global__ __launch_bounds__(256)
void tgemm_kernel(const float* __restrict__ A, const float* __restrict__ Bt,
                  float* __restrict__ C, int M, int N, int K,
                  int lda, int ldc, int mode, const float* __restrict__ bias)
{
    __shared__ float As[2][BM * SROW];
    __shared__ float Bs[2][BM * SROW];

    const int tid  = threadIdx.x;
    const int lane = tid & 31;
    const int wid  = tid >> 5;
    const int warp_m = wid & 3;
    const int warp_n = wid >> 2;
    const int row0 = blockIdx.y * BM;
    const int col0 = blockIdx.x * BN;

    /* staging mapping: thread -> 2 rows (r, r+64), 4 k-floats at sk */
    const int sr = tid >> 2;          /* 0..63 */
    const int sk = (tid & 3) << 2;    /* 0,4,8,12 */
    const float* Ap0 = A + (size_t)(row0 + sr) * lda + sk;
    const float* Ap1 = Ap0 + (size_t)64 * lda;
    const bool bv0 = (col0 + sr)      < N;
    const bool bv1 = (col0 + sr + 64) < N;
    const float* Bp0 = Bt + (size_t)(bv0 ? col0 + sr      : 0) * K + sk;
    const float* Bp1 = Bt + (size_t)(bv1 ? col0 + sr + 64 : 0) * K + sk;

    /* ldmatrix per-lane base byte offsets within a stage */
    const int L = lane;
    const uint32_t a_off =
        ((warp_m * 32 + (L & 7) + ((L >> 3) & 1) * 8) * SROW + ((L >> 4) & 1) * 4) * 4;
    const uint32_t b_off =
        ((warp_n * 64 + (L & 7) + ((L >> 4) & 1) * 8) * SROW + ((L >> 3) & 1) * 4) * 4;
    const uint32_t as_base = smem_u32(&As[0][0]);
    const uint32_t bs_base = smem_u32(&Bs[0][0]);

    float acc[2][8][4];
#pragma unroll
    for (int mt = 0; mt < 2; mt++)
#pragma unroll
        for (int nt = 0; nt < 8; nt++)
#pragma unroll
            for (int i = 0; i < 4; i++) acc[mt][nt][i] = 0.f;

    const float4 zero4 = make_float4(0.f, 0.f, 0.f, 0.f);

    /* prologue: stage slab 0 */
    {
        float4 va0 = *reinterpret_cast<const float4*>(Ap0);
        float4 va1 = *reinterpret_cast<const float4*>(Ap1);
        float4 vb0 = bv0 ? *reinterpret_cast<const float4*>(Bp0) : zero4;
        float4 vb1 = bv1 ? *reinterpret_cast<const float4*>(Bp1) : zero4;
        uint4 ta0 = make_uint4(f2tf(va0.x), f2tf(va0.y), f2tf(va0.z), f2tf(va0.w));
        uint4 ta1 = make_uint4(f2tf(va1.x), f2tf(va1.y), f2tf(va1.z), f2tf(va1.w));
        *reinterpret_cast<uint4*>(&As[0][sr * SROW + sk])        = ta0;
        *reinterpret_cast<uint4*>(&As[0][(sr + 64) * SROW + sk]) = ta1;
        *reinterpret_cast<float4*>(&Bs[0][sr * SROW + sk])        = vb0;
        *reinterpret_cast<float4*>(&Bs[0][(sr + 64) * SROW + sk]) = vb1;
    }
    __syncthreads();

    const int nslab = K / BK;
    for (int s = 0; s < nslab; s++) {
        const int buf = s & 1;
        float4 na0, na1, nb0, nb1;
        if (s + 1 < nslab) {
            int ko = (s + 1) * BK;
            na0 = *reinterpret_cast<const float4*>(Ap0 + ko);
            na1 = *reinterpret_cast<const float4*>(Ap1 + ko);
            nb0 = bv0 ? *reinterpret_cast<const float4*>(Bp0 + ko) : zero4;
            nb1 = bv1 ? *reinterpret_cast<const float4*>(Bp1 + ko) : zero4;
        }

        const uint32_t ab = as_base + buf * STAGE_B;
        const uint32_t bb = bs_base + buf * STAGE_B;
#pragma unroll
        for (int ks = 0; ks < 2; ks++) {
            uint32_t af[2][4], bf[4][4];
            LDSM4(af[0], ab + a_off + 0 * (16 * SROW * 4) + ks * 32);
            LDSM4(af[1], ab + a_off + 1 * (16 * SROW * 4) + ks * 32);
#pragma unroll
            for (int p = 0; p < 4; p++)
                LDSM4(bf[p], bb + b_off + p * (16 * SROW * 4) + ks * 32);
#pragma unroll
            for (int mt = 0; mt < 2; mt++)
#pragma unroll
                for (int p = 0; p < 4; p++) {
                    mma_tf32(acc[mt][2 * p + 0], af[mt], &bf[p][0]);
                    mma_tf32(acc[mt][2 * p + 1], af[mt], &bf[p][2]);
                }
        }

        if (s + 1 < nslab) {
            const int nb = buf ^ 1;
            uint4 ta0 = make_uint4(f2tf(na0.x), f2tf(na0.y), f2tf(na0.z), f2tf(na0.w));
            uint4 ta1 = make_uint4(f2tf(na1.x), f2tf(na1.y), f2tf(na1.z), f2tf(na1.w));
            *reinterpret_cast<uint4*>(&As[nb][sr * SROW + sk])        = ta0;
            *reinterpret_cast<uint4*>(&As[nb][(sr + 64) * SROW + sk]) = ta1;
            *reinterpret_cast<float4*>(&Bs[nb][sr * SROW + sk])        = nb0;
            *reinterpret_cast<float4*>(&Bs[nb][(sr + 64) * SROW + sk]) = nb1;
        }
        __syncthreads();
    }

    /* epilogue */
#pragma unroll
    for (int mt = 0; mt < 2; mt++) {
        int row = row0 + warp_m * 32 + mt * 16 + (lane >> 2);
#pragma unroll
        for (int nt = 0; nt < 8; nt++) {
            int col = col0 + warp_n * 64 + nt * 8 + (lane & 3) * 2;
            if (col < N) {
#pragma unroll
                for (int half = 0; half < 2; half++) {
                    int r = row + half * 8;
                    float v0 = acc[mt][nt][half * 2 + 0];
                    float v1 = acc[mt][nt][half * 2 + 1];
                    if (mode == 1) {
                        v0 += 2.f * bias[col];
                        v1 += 2.f * bias[col + 1];
                        v0 = (v0 > 20.f) ? v0 : log1pf(__expf(v0));
                        v1 = (v1 > 20.f) ? v1 : log1pf(__expf(v1));
                    } else if (mode == 2) {
                        v0 += bias[col];
                        v1 += bias[col + 1];
                    }
                    *reinterpret_cast<float2*>(&C[(size_t)r * ldc + col]) =
                        make_float2(v0, v1);
                }
            }
        }
    }
}

/* ------------------------------------------------------------------ */
/* Depthwise conv1d (k=4, SAME: pad_lo=1, pad_hi=2) + SiLU on both     */
/* halves of xz. xs -> g_u, z -> right half of g_cat.                  */
/* ------------------------------------------------------------------ */
__global__ __launch_bounds__(256)
void conv_silu_kernel(const float* __restrict__ wx, const float* __restrict__ bx,
                      const float* __restrict__ wz, const float* __restrict__ bz)
{
    int idx = blockIdx.x * blockDim.x + threadIdx.x;
    if (idx >= B_SZ * LSEQ * D_INNER) return;
    int c = idx % D_INNER;
    int l = (idx / D_INNER) % LSEQ;
    int b = idx / (D_INNER * LSEQ);

    bool isx = (c < D_HALF);
    int ch = isx ? c : c - D_HALF;
    const float* w = isx ? wx : wz;
    float acc = isx ? bx[ch] : bz[ch];

#pragma unroll
    for (int j = 0; j < 4; j++) {
        int ll = l + j - 1;
        if (ll >= 0 && ll < LSEQ)
            acc = fmaf(w[j * D_HALF + ch],
                       g_xz[((size_t)(b * LSEQ + ll)) * D_INNER + c], acc);
    }
    float s = acc / (1.f + __expf(-acc));   /* SiLU */

    size_t row = (size_t)(b * LSEQ + l);
    if (isx) g_u[row * D_HALF + ch] = s;
    else     g_cat[row * D_INNER + D_HALF + ch] = s;
}

/* ------------------------------------------------------------------ */
/* Selective scan. One thread per (b, d). dA_n = e^(n+1), e=exp(-Δ).    */
/* ------------------------------------------------------------------ */
#define SCAN_T 64
__global__ __launch_bounds__(128)
void scan_kernel(const float* __restrict__ Dvec)
{
    int b = blockIdx.y;
    int d = blockIdx.x * blockDim.x + threadIdx.x;

    __shared__ float sBC[SCAN_T][32];

    float h[D_STATE];
#pragma unroll
    for (int n = 0; n < D_STATE; n++) h[n] = 0.f;

    const float Dd = Dvec[d];
    const float* up = g_u     + (size_t)b * LSEQ * D_HALF + d;
    const float* dp = g_delta + (size_t)b * LSEQ * D_HALF + d;
    const float* xp = g_xdbl  + (size_t)b * LSEQ * XDBL_W + DT_RANK;
    float*       yp = g_cat   + (size_t)b * LSEQ * D_INNER + d;

    for (int l0 = 0; l0 < LSEQ; l0 += SCAN_T) {
        __syncthreads();
        for (int i = threadIdx.x; i < SCAN_T * 32; i += blockDim.x)
            sBC[i >> 5][i & 31] = xp[(size_t)(l0 + (i >> 5)) * XDBL_W + (i & 31)];
        __syncthreads();

#pragma unroll 4
        for (int t = 0; t < SCAN_T; t++) {
            int l = l0 + t;
            float del = dp[(size_t)l * D_HALF];
            float uu  = up[(size_t)l * D_HALF];
            float e   = __expf(-del);
            float du  = del * uu;

            float pw[D_STATE];
            pw[0] = e;
#pragma unroll
            for (int n = 1; n < D_STATE; n++)
                pw[n] = pw[n >> 1] * pw[(n - 1) >> 1];

            float y = 0.f;
#pragma unroll
            for (int n = 0; n < D_STATE; n++) {
                h[n] = fmaf(h[n], pw[n], du * sBC[t][n]);
                y    = fmaf(h[n], sBC[t][16 + n], y);
            }
            yp[(size_t)l * D_INNER] = fmaf(uu, Dd, y);
        }
    }
}

/* ------------------------------------------------------------------ */
extern "C" void kernel_launch(void* const* d_in, const int* in_sizes, int n_in,
                              void* d_out, int out_size)
{
    const float* x        = (const float*)d_in[0];
    const float* W_in     = (const float*)d_in[1];
    const float* conv_x_w = (const float*)d_in[2];
    const float* conv_x_b = (const float*)d_in[3];
    const float* conv_z_w = (const float*)d_in[4];
    const float* conv_z_b = (const float*)d_in[5];
    const float* W_xdbl   = (const float*)d_in[6];
    const float* W_dt     = (const float*)d_in[7];
    const float* inv_dt   = (const float*)d_in[8];
    const float* Dvec     = (const float*)d_in[9];
    const float* W_out    = (const float*)d_in[10];
    const float* b_out    = (const float*)d_in[11];
    float* out = (float*)d_out;

    float *xz, *u, *xdbl, *delta, *cat, *bt;
    cudaGetSymbolAddress((void**)&xz,    g_xz);
    cudaGetSymbolAddress((void**)&u,     g_u);
    cudaGetSymbolAddress((void**)&xdbl,  g_xdbl);
    cudaGetSymbolAddress((void**)&delta, g_delta);
    cudaGetSymbolAddress((void**)&cat,   g_cat);
    cudaGetSymbolAddress((void**)&bt,    g_bt);

    dim3 tb(32, 8);

    /* 1. xz = x @ W_in : (8192,1024)@(1024,2048) */
    transpose_tf32_kernel<<<dim3(D_INNER / 32, D_MODEL / 32), tb>>>(W_in, bt, D_MODEL, D_INNER);
    tgemm_kernel<<<dim3(D_INNER / BN, ROWS / BM), 256>>>(
        x, bt, xz, ROWS, D_INNER, D_MODEL, D_MODEL, D_INNER, 0, nullptr);

    /* 2. depthwise conv + SiLU on both halves */
    conv_silu_kernel<<<(B_SZ * LSEQ * D_INNER) / 256, 256>>>(
        conv_x_w, conv_x_b, conv_z_w, conv_z_b);

    /* 3. x_dbl = u @ W_xdbl : (8192,1024)@(1024,96) */
    transpose_tf32_kernel<<<dim3(XDBL_W / 32 + 1, D_HALF / 32), tb>>>(W_xdbl, bt, D_HALF, XDBL_W);
    tgemm_kernel<<<dim3(1, ROWS / BM), 256>>>(
        u, bt, xdbl, ROWS, XDBL_W, D_HALF, D_HALF, XDBL_W, 0, nullptr);

    /* 4. delta = softplus(dt_low @ W_dt + 2*inv_dt) : (8192,64)@(64,1024) */
    transpose_tf32_kernel<<<dim3(D_HALF / 32, DT_RANK / 32), tb>>>(W_dt, bt, DT_RANK, D_HALF);
    tgemm_kernel<<<dim3(D_HALF / BN, ROWS / BM), 256>>>(
        xdbl, bt, delta, ROWS, D_HALF, DT_RANK, XDBL_W, D_HALF, 1, inv_dt);

    /* 5. selective scan -> y (left half of g_cat) */
    scan_kernel<<<dim3(D_HALF / 128, B_SZ), 128>>>(Dvec);

    /* 6. out = [y | z] @ W_out + b_out : (8192,2048)@(2048,1024) */
    transpose_tf32_kernel<<<dim3(D_MODEL / 32, D_INNER / 32), tb>>>(W_out, bt, D_INNER, D_MODEL);
    tgemm_kernel<<<dim3(D_MODEL / BN, ROWS / BM), 256>>>(
        cat, bt, out, ROWS, D_MODEL, D_INNER, D_INNER, D_MODEL, 2, b_out);
}

// round 9
// speedup vs baseline: 2.2273x; 2.2273x over previous
#include <cuda_runtime.h>
#include <math.h>
#include <stdint.h>

#define B_SZ    4
#define LSEQ    2048
#define D_MODEL 1024
#define D_INNER 2048
#define D_HALF  1024
#define D_STATE 16
#define DT_RANK 64
#define ROWS    (B_SZ * LSEQ)   /* 8192 */
#define XDBL_W  96              /* DT_RANK + 2*D_STATE */
#define NC      16              /* scan chunks */
#define CL      128             /* steps per chunk */

/* ------------------------------------------------------------------ */
/* Scratch (allocation-free rule: __device__ globals)                  */
/* ------------------------------------------------------------------ */
__device__ float g_xz   [ROWS * D_INNER];          /* 64 MB */
__device__ float g_u    [ROWS * D_HALF];           /* 32 MB xs after conv+silu */
__device__ float g_xdbl [ROWS * XDBL_W];           /*  3 MB [dt_low | B | C]   */
__device__ float g_e    [ROWS * D_HALF];           /* 32 MB exp(-delta)        */
__device__ float g_du   [ROWS * D_HALF];           /* 32 MB delta*u            */
__device__ float g_cat  [ROWS * D_INNER];          /* 64 MB [y | z]            */
__device__ float g_hloc [B_SZ * NC * D_STATE * D_HALF]; /* 4 MB chunk states  */
__device__ float g_P    [B_SZ * NC * D_HALF];      /* 256 KB chunk decay seeds */

__device__ __forceinline__ uint32_t f2tf(float x) {
    uint32_t r;
    asm("cvt.rna.tf32.f32 %0, %1;" : "=r"(r) : "f"(x));
    return r;
}

__device__ __forceinline__ void mma_tf32(float* c, const uint32_t* a, const uint32_t* b) {
    asm volatile(
        "mma.sync.aligned.m16n8k8.row.col.f32.tf32.tf32.f32 "
        "{%0,%1,%2,%3}, {%4,%5,%6,%7}, {%8,%9}, {%0,%1,%2,%3};"
        : "+f"(c[0]), "+f"(c[1]), "+f"(c[2]), "+f"(c[3])
        : "r"(a[0]), "r"(a[1]), "r"(a[2]), "r"(a[3]), "r"(b[0]), "r"(b[1]));
}

/* ------------------------------------------------------------------ */
/* TF32 tensor-core GEMM (R2-proven layout): C = A(MxK) @ B(KxN).      */
/* mode 0: plain C=v.                                                  */
/* mode 1: delta-epilogue: v+=2*bias; delta=softplus(v);               */
/*         C = exp(-delta) = 1/(1+e^v);  C2 = delta * U[row,col].      */
/* mode 2: C = v + bias[col].                                          */
/* CTA tile 128x128x16, 8 warps, warp tile 32x64, mma.m16n8k8.tf32.    */
/* ------------------------------------------------------------------ */
#define BM 128
#define BN 128
#define BK 16
#define SA 20
#define SB 136

__global__ __launch_bounds__(256)
void tgemm_kernel(const float* __restrict__ A, const float* __restrict__ B,
                  float* __restrict__ C, int M, int N, int K,
                  int lda, int ldb, int ldc,
                  int mode, const float* __restrict__ bias,
                  const float* __restrict__ U, float* __restrict__ C2)
{
    __shared__ uint32_t As[BM * SA];
    __shared__ uint32_t Bs[BK * SB];

    const int tid    = threadIdx.x;
    const int lane   = tid & 31;
    const int wid    = tid >> 5;
    const int warp_m = wid & 3;
    const int warp_n = wid >> 2;
    const int block_row = blockIdx.y * BM;
    const int block_col = blockIdx.x * BN;

    float acc[2][8][4];
#pragma unroll
    for (int mt = 0; mt < 2; mt++)
#pragma unroll
        for (int nt = 0; nt < 8; nt++)
#pragma unroll
            for (int i = 0; i < 4; i++) acc[mt][nt][i] = 0.f;

    const int a_r = tid >> 2;
    const int a_k = (tid & 3) << 2;
    const int b_r = tid >> 5;
    const int b_c = (tid & 31) << 2;

    for (int k0 = 0; k0 < K; k0 += BK) {
#pragma unroll
        for (int i = 0; i < 2; i++) {
            int r = a_r + i * 64;
            float4 v = *reinterpret_cast<const float4*>(
                &A[(size_t)(block_row + r) * lda + k0 + a_k]);
            As[r * SA + a_k + 0] = f2tf(v.x);
            As[r * SA + a_k + 1] = f2tf(v.y);
            As[r * SA + a_k + 2] = f2tf(v.z);
            As[r * SA + a_k + 3] = f2tf(v.w);
        }
#pragma unroll
        for (int i = 0; i < 2; i++) {
            int r = b_r + i * 8;
            int col = block_col + b_c;
            float4 v = make_float4(0.f, 0.f, 0.f, 0.f);
            if (col < N)
                v = *reinterpret_cast<const float4*>(&B[(size_t)(k0 + r) * ldb + col]);
            uint4 t;
            t.x = f2tf(v.x); t.y = f2tf(v.y); t.z = f2tf(v.z); t.w = f2tf(v.w);
            *reinterpret_cast<uint4*>(&Bs[r * SB + b_c]) = t;
        }
        __syncthreads();

#pragma unroll
        for (int ks = 0; ks < 2; ks++) {
            uint32_t af[2][4];
            uint32_t bf[8][2];
            const int row0 = warp_m * 32 + (lane >> 2);
            const int kk   = ks * 8 + (lane & 3);
#pragma unroll
            for (int mt = 0; mt < 2; mt++) {
                int r = row0 + mt * 16;
                af[mt][0] = As[r * SA + kk];
                af[mt][1] = As[(r + 8) * SA + kk];
                af[mt][2] = As[r * SA + kk + 4];
                af[mt][3] = As[(r + 8) * SA + kk + 4];
            }
            const int coln = warp_n * 64 + (lane >> 2);
#pragma unroll
            for (int nt = 0; nt < 8; nt++) {
                bf[nt][0] = Bs[(ks * 8 + (lane & 3)) * SB + coln + nt * 8];
                bf[nt][1] = Bs[(ks * 8 + 4 + (lane & 3)) * SB + coln + nt * 8];
            }
#pragma unroll
            for (int mt = 0; mt < 2; mt++)
#pragma unroll
                for (int nt = 0; nt < 8; nt++)
                    mma_tf32(acc[mt][nt], af[mt], bf[nt]);
        }
        __syncthreads();
    }

#pragma unroll
    for (int mt = 0; mt < 2; mt++) {
        int row = block_row + warp_m * 32 + mt * 16 + (lane >> 2);
#pragma unroll
        for (int nt = 0; nt < 8; nt++) {
            int col = block_col + warp_n * 64 + nt * 8 + (lane & 3) * 2;
            if (col < N) {
#pragma unroll
                for (int half = 0; half < 2; half++) {
                    int r = row + half * 8;
                    float v0 = acc[mt][nt][half * 2 + 0];
                    float v1 = acc[mt][nt][half * 2 + 1];
                    if (mode == 1) {
                        v0 += 2.f * bias[col];
                        v1 += 2.f * bias[col + 1];
                        float t0 = __expf(v0), t1 = __expf(v1);
                        float d0 = (v0 > 20.f) ? v0 : log1pf(t0);
                        float d1 = (v1 > 20.f) ? v1 : log1pf(t1);
                        float e0 = __fdividef(1.f, 1.f + t0);
                        float e1 = __fdividef(1.f, 1.f + t1);
                        float2 uu = *reinterpret_cast<const float2*>(
                            &U[(size_t)r * ldc + col]);
                        *reinterpret_cast<float2*>(&C[(size_t)r * ldc + col]) =
                            make_float2(e0, e1);
                        *reinterpret_cast<float2*>(&C2[(size_t)r * ldc + col]) =
                            make_float2(d0 * uu.x, d1 * uu.y);
                        continue;
                    }
                    if (mode == 2) {
                        v0 += bias[col];
                        v1 += bias[col + 1];
                    }
                    *reinterpret_cast<float2*>(&C[(size_t)r * ldc + col]) =
                        make_float2(v0, v1);
                }
            }
        }
    }
}

/* ------------------------------------------------------------------ */
/* Depthwise conv1d (k=4, SAME) + SiLU. xs -> g_u, z -> g_cat right.   */
/* ------------------------------------------------------------------ */
__global__ __launch_bounds__(256)
void conv_silu_kernel(const float* __restrict__ wx, const float* __restrict__ bx,
                      const float* __restrict__ wz, const float* __restrict__ bz)
{
    int idx = blockIdx.x * blockDim.x + threadIdx.x;
    if (idx >= B_SZ * LSEQ * D_INNER) return;
    int c = idx % D_INNER;
    int l = (idx / D_INNER) % LSEQ;
    int b = idx / (D_INNER * LSEQ);

    bool isx = (c < D_HALF);
    int ch = isx ? c : c - D_HALF;
    const float* w = isx ? wx : wz;
    float acc = isx ? bx[ch] : bz[ch];

#pragma unroll
    for (int j = 0; j < 4; j++) {
        int ll = l + j - 1;
        if (ll >= 0 && ll < LSEQ)
            acc = fmaf(w[j * D_HALF + ch],
                       g_xz[((size_t)(b * LSEQ + ll)) * D_INNER + c], acc);
    }
    float s = acc / (1.f + __expf(-acc));

    size_t row = (size_t)(b * LSEQ + l);
    if (isx) g_u[row * D_HALF + ch] = s;
    else     g_cat[row * D_INNER + D_HALF + ch] = s;
}

/* ------------------------------------------------------------------ */
/* Parallel scan, pass 1: per (b, chunk, d) compute local final state  */
/* hloc[16] (h starting at 0) and decay seed P = prod(e_t).            */
/* Grid: (D_HALF/128, NC, B_SZ), block 128. exp-free (e precomputed).  */
/* ------------------------------------------------------------------ */
__global__ __launch_bounds__(128)
void scan_pass1_kernel()
{
    const int tid = threadIdx.x;
    const int b = blockIdx.z, c = blockIdx.y;
    const int d = blockIdx.x * 128 + tid;

    __shared__ float sB[CL][D_STATE];
    const int base_row = b * LSEQ + c * CL;
    for (int i = tid; i < CL * D_STATE; i += 128)
        sB[i >> 4][i & 15] =
            g_xdbl[(size_t)(base_row + (i >> 4)) * XDBL_W + DT_RANK + (i & 15)];
    __syncthreads();

    const float* ep  = g_e  + (size_t)base_row * D_HALF + d;
    const float* dup = g_du + (size_t)base_row * D_HALF + d;

    float h[D_STATE];
#pragma unroll
    for (int n = 0; n < D_STATE; n++) h[n] = 0.f;
    float P = 1.f;

#pragma unroll 4
    for (int t = 0; t < CL; t++) {
        float e  = ep [(size_t)t * D_HALF];
        float du = dup[(size_t)t * D_HALF];
        float pw[D_STATE];
        pw[0] = e;
#pragma unroll
        for (int n = 1; n < D_STATE; n++)
            pw[n] = pw[n >> 1] * pw[(n - 1) >> 1];
#pragma unroll
        for (int n = 0; n < D_STATE; n++)
            h[n] = fmaf(h[n], pw[n], du * sB[t][n]);
        P *= e;
    }

    const size_t hbase = ((size_t)(b * NC + c) * D_STATE) * D_HALF + d;
#pragma unroll
    for (int n = 0; n < D_STATE; n++)
        g_hloc[hbase + (size_t)n * D_HALF] = h[n];
    g_P[(size_t)(b * NC + c) * D_HALF + d] = P;
}

/* ------------------------------------------------------------------ */
/* Parallel scan, pass 2: compose h0 from prior chunk summaries, then  */
/* rerun local scan emitting y into left half of g_cat.                */
/* ------------------------------------------------------------------ */
__global__ __launch_bounds__(128)
void scan_pass2_kernel(const float* __restrict__ Dvec)
{
    const int tid = threadIdx.x;
    const int b = blockIdx.z, c = blockIdx.y;
    const int d = blockIdx.x * 128 + tid;

    __shared__ float sB[CL][D_STATE];
    __shared__ float sC[CL][D_STATE];
    const int base_row = b * LSEQ + c * CL;
    for (int i = tid; i < CL * D_STATE; i += 128) {
        size_t src = (size_t)(base_row + (i >> 4)) * XDBL_W + DT_RANK + (i & 15);
        sB[i >> 4][i & 15] = g_xdbl[src];
        sC[i >> 4][i & 15] = g_xdbl[src + D_STATE];
    }
    __syncthreads();

    /* compose incoming state from chunks 0..c-1 */
    float h[D_STATE];
#pragma unroll
    for (int n = 0; n < D_STATE; n++) h[n] = 0.f;
    for (int j = 0; j < c; j++) {
        float Pj = g_P[(size_t)(b * NC + j) * D_HALF + d];
        float pw[D_STATE];
        pw[0] = Pj;
#pragma unroll
        for (int n = 1; n < D_STATE; n++)
            pw[n] = pw[n >> 1] * pw[(n - 1) >> 1];
        const size_t hbase = ((size_t)(b * NC + j) * D_STATE) * D_HALF + d;
#pragma unroll
        for (int n = 0; n < D_STATE; n++)
            h[n] = fmaf(h[n], pw[n], g_hloc[hbase + (size_t)n * D_HALF]);
    }

    const float Dd = Dvec[d];
    const float* ep  = g_e  + (size_t)base_row * D_HALF + d;
    const float* dup = g_du + (size_t)base_row * D_HALF + d;
    const float* up  = g_u  + (size_t)base_row * D_HALF + d;
    float*       yp  = g_cat + (size_t)base_row * D_INNER + d;

#pragma unroll 4
    for (int t = 0; t < CL; t++) {
        float e  = ep [(size_t)t * D_HALF];
        float du = dup[(size_t)t * D_HALF];
        float uu = up [(size_t)t * D_HALF];
        float pw[D_STATE];
        pw[0] = e;
#pragma unroll
        for (int n = 1; n < D_STATE; n++)
            pw[n] = pw[n >> 1] * pw[(n - 1) >> 1];
        float y = 0.f;
#pragma unroll
        for (int n = 0; n < D_STATE; n++) {
            h[n] = fmaf(h[n], pw[n], du * sB[t][n]);
            y    = fmaf(h[n], sC[t][n], y);
        }
        yp[(size_t)t * D_INNER] = fmaf(uu, Dd, y);
    }
}

/* ------------------------------------------------------------------ */
extern "C" void kernel_launch(void* const* d_in, const int* in_sizes, int n_in,
                              void* d_out, int out_size)
{
    const float* x        = (const float*)d_in[0];
    const float* W_in     = (const float*)d_in[1];
    const float* conv_x_w = (const float*)d_in[2];
    const float* conv_x_b = (const float*)d_in[3];
    const float* conv_z_w = (const float*)d_in[4];
    const float* conv_z_b = (const float*)d_in[5];
    const float* W_xdbl   = (const float*)d_in[6];
    const float* W_dt     = (const float*)d_in[7];
    const float* inv_dt   = (const float*)d_in[8];
    const float* Dvec     = (const float*)d_in[9];
    const float* W_out    = (const float*)d_in[10];
    const float* b_out    = (const float*)d_in[11];
    float* out = (float*)d_out;

    float *xz, *u, *xdbl, *e, *du, *cat;
    cudaGetSymbolAddress((void**)&xz,   g_xz);
    cudaGetSymbolAddress((void**)&u,    g_u);
    cudaGetSymbolAddress((void**)&xdbl, g_xdbl);
    cudaGetSymbolAddress((void**)&e,    g_e);
    cudaGetSymbolAddress((void**)&du,   g_du);
    cudaGetSymbolAddress((void**)&cat,  g_cat);

    /* 1. xz = x @ W_in : (8192,1024)@(1024,2048) */
    tgemm_kernel<<<dim3(D_INNER / BN, ROWS / BM), 256>>>(
        x, W_in, xz, ROWS, D_INNER, D_MODEL,
        D_MODEL, D_INNER, D_INNER, 0, nullptr, nullptr, nullptr);

    /* 2. depthwise conv + SiLU on both halves */
    conv_silu_kernel<<<(B_SZ * LSEQ * D_INNER) / 256, 256>>>(
        conv_x_w, conv_x_b, conv_z_w, conv_z_b);

    /* 3. x_dbl = u @ W_xdbl : (8192,1024)@(1024,96) */
    tgemm_kernel<<<dim3(1, ROWS / BM), 256>>>(
        u, W_xdbl, xdbl, ROWS, XDBL_W, D_HALF,
        D_HALF, XDBL_W, XDBL_W, 0, nullptr, nullptr, nullptr);

    /* 4. delta GEMM + fused epilogue -> e = exp(-delta), du = delta*u */
    tgemm_kernel<<<dim3(D_HALF / BN, ROWS / BM), 256>>>(
        xdbl, W_dt, e, ROWS, D_HALF, DT_RANK,
        XDBL_W, D_HALF, D_HALF, 1, inv_dt, u, du);

    /* 5. parallel selective scan -> y (left half of g_cat) */
    scan_pass1_kernel<<<dim3(D_HALF / 128, NC, B_SZ), 128>>>();
    scan_pass2_kernel<<<dim3(D_HALF / 128, NC, B_SZ), 128>>>(Dvec);

    /* 6. out = [y | z] @ W_out + b_out : (8192,2048)@(2048,1024) */
    tgemm_kernel<<<dim3(D_MODEL / BN, ROWS / BM), 256>>>(
        cat, W_out, out, ROWS, D_MODEL, D_INNER,
        D_INNER, D_MODEL, D_MODEL, 2, b_out, nullptr, nullptr);
}

// round 12
// speedup vs baseline: 2.8390x; 1.2747x over previous
#include <cuda_runtime.h>
#include <math.h>
#include <stdint.h>

#define B_SZ    4
#define LSEQ    2048
#define D_MODEL 1024
#define D_INNER 2048
#define D_HALF  1024
#define D_STATE 16
#define DT_RANK 64
#define ROWS    (B_SZ * LSEQ)   /* 8192 */
#define XDBL_W  96              /* DT_RANK + 2*D_STATE */
#define NC      16              /* scan chunks */
#define CL      128             /* steps per chunk */

/* ------------------------------------------------------------------ */
/* Scratch (allocation-free rule: __device__ globals)                  */
/* ------------------------------------------------------------------ */
__device__ float g_xz   [ROWS * D_INNER];          /* 64 MB */
__device__ float g_u    [ROWS * D_HALF];           /* 32 MB xs (tf32-rounded) */
__device__ float g_xdbl [ROWS * XDBL_W];           /*  3 MB (tf32-rounded)    */
__device__ float g_e    [ROWS * D_HALF];           /* 32 MB exp(-delta)       */
__device__ float g_du   [ROWS * D_HALF];           /* 32 MB delta*u           */
__device__ float g_cat  [ROWS * D_INNER];          /* 64 MB [y | z] rounded   */
__device__ float g_hloc [B_SZ * NC * D_STATE * D_HALF]; /* 4 MB */
__device__ float g_P    [B_SZ * NC * D_HALF];      /* 256 KB */
__device__ float g_x32  [ROWS * D_MODEL];          /* 32 MB tf32-rounded x    */
__device__ float g_wr   [4 * 1024 * 1024 + 98304 + 65536]; /* rounded weights */

#define WR_IN 0
#define WR_OUT (2 * 1024 * 1024)
#define WR_XD  (4 * 1024 * 1024)
#define WR_DT  (4 * 1024 * 1024 + 98304)

__device__ __forceinline__ uint32_t f2tf(float x) {
    uint32_t r;
    asm("cvt.rna.tf32.f32 %0, %1;" : "=r"(r) : "f"(x));
    return r;
}
__device__ __forceinline__ float f2tff(float x) { return __uint_as_float(f2tf(x)); }

__device__ __forceinline__ uint32_t smem_u32(const void* p) {
    return (uint32_t)__cvta_generic_to_shared(p);
}

__device__ __forceinline__ void cpa16(uint32_t dst, const float* src, int sz) {
    asm volatile("cp.async.cg.shared.global [%0], [%1], 16, %2;"
                 :: "r"(dst), "l"(src), "r"(sz));
}
__device__ __forceinline__ void cpa_commit() {
    asm volatile("cp.async.commit_group;");
}
template <int N>
__device__ __forceinline__ void cpa_wait() {
    asm volatile("cp.async.wait_group %0;" :: "n"(N));
}

__device__ __forceinline__ void mma_tf32(float* c, const uint32_t* a, const uint32_t* b) {
    asm volatile(
        "mma.sync.aligned.m16n8k8.row.col.f32.tf32.tf32.f32 "
        "{%0,%1,%2,%3}, {%4,%5,%6,%7}, {%8,%9}, {%0,%1,%2,%3};"
        : "+f"(c[0]), "+f"(c[1]), "+f"(c[2]), "+f"(c[3])
        : "r"(a[0]), "r"(a[1]), "r"(a[2]), "r"(a[3]), "r"(b[0]), "r"(b[1]));
}

/* ------------------------------------------------------------------ */
/* tf32 round-copy: out[i] = rna_tf32(in[i]), n % 4 == 0               */
/* ------------------------------------------------------------------ */
__global__ __launch_bounds__(256)
void round_tf32_kernel(const float* __restrict__ in, float* __restrict__ out, int n4)
{
    int i = blockIdx.x * blockDim.x + threadIdx.x;
    if (i < n4) {
        float4 v = reinterpret_cast<const float4*>(in)[i];
        v.x = f2tff(v.x); v.y = f2tff(v.y); v.z = f2tff(v.z); v.w = f2tff(v.w);
        reinterpret_cast<float4*>(out)[i] = v;
    }
}

/* ------------------------------------------------------------------ */
/* TF32 GEMM, cp.async double-buffered. Operands MUST be pre-rounded.  */
/* C = A(MxK) @ B(KxN) row-major.                                      */
/* mode 0: C=v; 3: C=tf32(v);                                          */
/* mode 1: delta-epilogue: v+=2*bias; C=1/(1+e^v); C2=softplus(v)*U.   */
/* mode 2: C=v+bias[col].                                              */
/* ------------------------------------------------------------------ */
#define BM 128
#define BN 128
#define BK 16
#define SA 20
#define SB 136
#define A_ST_B (BM * SA * 4)   /* 10240 bytes */
#define B_ST_B (BK * SB * 4)   /*  8704 bytes */

__global__ __launch_bounds__(256)
void tgemm_kernel(const float* __restrict__ A, const float* __restrict__ B,
                  float* __restrict__ C, int M, int N, int K,
                  int lda, int ldb, int ldc,
                  int mode, const float* __restrict__ bias,
                  const float* __restrict__ U, float* __restrict__ C2)
{
    __shared__ float As[2][BM * SA];
    __shared__ float Bs[2][BK * SB];

    const int tid    = threadIdx.x;
    const int lane   = tid & 31;
    const int wid    = tid >> 5;
    const int warp_m = wid & 3;
    const int warp_n = wid >> 2;
    const int block_row = blockIdx.y * BM;
    const int block_col = blockIdx.x * BN;

    float acc[2][8][4];
#pragma unroll
    for (int mt = 0; mt < 2; mt++)
#pragma unroll
        for (int nt = 0; nt < 8; nt++)
#pragma unroll
            for (int i = 0; i < 4; i++) acc[mt][nt][i] = 0.f;

    /* staging mapping */
    const int a_r = tid >> 2;            /* 0..63 */
    const int a_k = (tid & 3) << 2;      /* 0,4,8,12 */
    const int b_r = tid >> 5;            /* 0..7  */
    const int b_c = (tid & 31) << 2;     /* 0..124 */
    const int colg = block_col + b_c;
    const int szb  = (colg < N) ? 16 : 0;
    const int colc = (colg < N) ? colg : 0;

    const float* Ap0 = A + (size_t)(block_row + a_r) * lda + a_k;
    const float* Ap1 = Ap0 + (size_t)64 * lda;
    const float* Bp0 = B + (size_t)b_r * ldb + colc;
    const float* Bp1 = B + (size_t)(b_r + 8) * ldb + colc;

    const uint32_t aD0 = smem_u32(&As[0][a_r * SA + a_k]);
    const uint32_t aD1 = smem_u32(&As[0][(a_r + 64) * SA + a_k]);
    const uint32_t bD0 = smem_u32(&Bs[0][b_r * SB + b_c]);
    const uint32_t bD1 = smem_u32(&Bs[0][(b_r + 8) * SB + b_c]);

    const int nslab = K / BK;

    /* prologue: stage slab 0 into buf 0 */
    cpa16(aD0, Ap0, 16);
    cpa16(aD1, Ap1, 16);
    cpa16(bD0, Bp0, szb);
    cpa16(bD1, Bp1, szb);
    cpa_commit();

    for (int s = 0; s < nslab; s++) {
        const int buf = s & 1;
        if (s + 1 < nslab) {
            const int nb = buf ^ 1;
            const int ko = (s + 1) * BK;
            const size_t kob = (size_t)ko * ldb;
            cpa16(aD0 + nb * A_ST_B, Ap0 + ko, 16);
            cpa16(aD1 + nb * A_ST_B, Ap1 + ko, 16);
            cpa16(bD0 + nb * B_ST_B, Bp0 + kob, szb);
            cpa16(bD1 + nb * B_ST_B, Bp1 + kob, szb);
            cpa_commit();
            cpa_wait<1>();
        } else {
            cpa_wait<0>();
        }
        __syncthreads();

        const uint32_t* Asb = reinterpret_cast<const uint32_t*>(As[buf]);
        const uint32_t* Bsb = reinterpret_cast<const uint32_t*>(Bs[buf]);
#pragma unroll
        for (int ks = 0; ks < 2; ks++) {
            uint32_t af[2][4];
            uint32_t bf[8][2];
            const int row0 = warp_m * 32 + (lane >> 2);
            const int kk   = ks * 8 + (lane & 3);
#pragma unroll
            for (int mt = 0; mt < 2; mt++) {
                int r = row0 + mt * 16;
                af[mt][0] = Asb[r * SA + kk];
                af[mt][1] = Asb[(r + 8) * SA + kk];
                af[mt][2] = Asb[r * SA + kk + 4];
                af[mt][3] = Asb[(r + 8) * SA + kk + 4];
            }
            const int coln = warp_n * 64 + (lane >> 2);
#pragma unroll
            for (int nt = 0; nt < 8; nt++) {
                bf[nt][0] = Bsb[(ks * 8 + (lane & 3)) * SB + coln + nt * 8];
                bf[nt][1] = Bsb[(ks * 8 + 4 + (lane & 3)) * SB + coln + nt * 8];
            }
#pragma unroll
            for (int mt = 0; mt < 2; mt++)
#pragma unroll
                for (int nt = 0; nt < 8; nt++)
                    mma_tf32(acc[mt][nt], af[mt], bf[nt]);
        }
        __syncthreads();
    }

#pragma unroll
    for (int mt = 0; mt < 2; mt++) {
        int row = block_row + warp_m * 32 + mt * 16 + (lane >> 2);
#pragma unroll
        for (int nt = 0; nt < 8; nt++) {
            int col = block_col + warp_n * 64 + nt * 8 + (lane & 3) * 2;
            if (col < N) {
#pragma unroll
                for (int half = 0; half < 2; half++) {
                    int r = row + half * 8;
                    float v0 = acc[mt][nt][half * 2 + 0];
                    float v1 = acc[mt][nt][half * 2 + 1];
                    if (mode == 1) {
                        v0 += 2.f * bias[col];
                        v1 += 2.f * bias[col + 1];
                        float t0 = __expf(v0), t1 = __expf(v1);
                        float d0 = (v0 > 20.f) ? v0 : log1pf(t0);
                        float d1 = (v1 > 20.f) ? v1 : log1pf(t1);
                        float e0 = __fdividef(1.f, 1.f + t0);
                        float e1 = __fdividef(1.f, 1.f + t1);
                        float2 uu = *reinterpret_cast<const float2*>(
                            &U[(size_t)r * ldc + col]);
                        *reinterpret_cast<float2*>(&C[(size_t)r * ldc + col]) =
                            make_float2(e0, e1);
                        *reinterpret_cast<float2*>(&C2[(size_t)r * ldc + col]) =
                            make_float2(d0 * uu.x, d1 * uu.y);
                        continue;
                    }
                    if (mode == 2) {
                        v0 += bias[col];
                        v1 += bias[col + 1];
                    } else if (mode == 3) {
                        v0 = f2tff(v0);
                        v1 = f2tff(v1);
                    }
                    *reinterpret_cast<float2*>(&C[(size_t)r * ldc + col]) =
                        make_float2(v0, v1);
                }
            }
        }
    }
}

/* ------------------------------------------------------------------ */
/* Depthwise conv1d (k=4, SAME) + SiLU. Writes tf32-rounded outputs.   */
/* ------------------------------------------------------------------ */
__global__ __launch_bounds__(256)
void conv_silu_kernel(const float* __restrict__ wx, const float* __restrict__ bx,
                      const float* __restrict__ wz, const float* __restrict__ bz)
{
    int idx = blockIdx.x * blockDim.x + threadIdx.x;
    if (idx >= B_SZ * LSEQ * D_INNER) return;
    int c = idx % D_INNER;
    int l = (idx / D_INNER) % LSEQ;
    int b = idx / (D_INNER * LSEQ);

    bool isx = (c < D_HALF);
    int ch = isx ? c : c - D_HALF;
    const float* w = isx ? wx : wz;
    float acc = isx ? bx[ch] : bz[ch];

#pragma unroll
    for (int j = 0; j < 4; j++) {
        int ll = l + j - 1;
        if (ll >= 0 && ll < LSEQ)
            acc = fmaf(w[j * D_HALF + ch],
                       g_xz[((size_t)(b * LSEQ + ll)) * D_INNER + c], acc);
    }
    float s = f2tff(acc / (1.f + __expf(-acc)));

    size_t row = (size_t)(b * LSEQ + l);
    if (isx) g_u[row * D_HALF + ch] = s;
    else     g_cat[row * D_INNER + D_HALF + ch] = s;
}

/* ------------------------------------------------------------------ */
/* Parallel scan pass 1                                                */
/* ------------------------------------------------------------------ */
__global__ __launch_bounds__(128)
void scan_pass1_kernel()
{
    const int tid = threadIdx.x;
    const int b = blockIdx.z, c = blockIdx.y;
    const int d = blockIdx.x * 128 + tid;

    __shared__ float sB[CL][D_STATE];
    const int base_row = b * LSEQ + c * CL;
    for (int i = tid; i < CL * D_STATE; i += 128)
        sB[i >> 4][i & 15] =
            g_xdbl[(size_t)(base_row + (i >> 4)) * XDBL_W + DT_RANK + (i & 15)];
    __syncthreads();

    const float* ep  = g_e  + (size_t)base_row * D_HALF + d;
    const float* dup = g_du + (size_t)base_row * D_HALF + d;

    float h[D_STATE];
#pragma unroll
    for (int n = 0; n < D_STATE; n++) h[n] = 0.f;
    float P = 1.f;

#pragma unroll 4
    for (int t = 0; t < CL; t++) {
        float e  = ep [(size_t)t * D_HALF];
        float du = dup[(size_t)t * D_HALF];
        float pw[D_STATE];
        pw[0] = e;
#pragma unroll
        for (int n = 1; n < D_STATE; n++)
            pw[n] = pw[n >> 1] * pw[(n - 1) >> 1];
#pragma unroll
        for (int n = 0; n < D_STATE; n++)
            h[n] = fmaf(h[n], pw[n], du * sB[t][n]);
        P *= e;
    }

    const size_t hbase = ((size_t)(b * NC + c) * D_STATE) * D_HALF + d;
#pragma unroll
    for (int n = 0; n < D_STATE; n++)
        g_hloc[hbase + (size_t)n * D_HALF] = h[n];
    g_P[(size_t)(b * NC + c) * D_HALF + d] = P;
}

/* ------------------------------------------------------------------ */
/* Parallel scan pass 2 (emits tf32-rounded y)                         */
/* ------------------------------------------------------------------ */
__global__ __launch_bounds__(128)
void scan_pass2_kernel(const float* __restrict__ Dvec)
{
    const int tid = threadIdx.x;
    const int b = blockIdx.z, c = blockIdx.y;
    const int d = blockIdx.x * 128 + tid;

    __shared__ float sB[CL][D_STATE];
    __shared__ float sC[CL][D_STATE];
    const int base_row = b * LSEQ + c * CL;
    for (int i = tid; i < CL * D_STATE; i += 128) {
        size_t src = (size_t)(base_row + (i >> 4)) * XDBL_W + DT_RANK + (i & 15);
        sB[i >> 4][i & 15] = g_xdbl[src];
        sC[i >> 4][i & 15] = g_xdbl[src + D_STATE];
    }
    __syncthreads();

    float h[D_STATE];
#pragma unroll
    for (int n = 0; n < D_STATE; n++) h[n] = 0.f;
    for (int j = 0; j < c; j++) {
        float Pj = g_P[(size_t)(b * NC + j) * D_HALF + d];
        float pw[D_STATE];
        pw[0] = Pj;
#pragma unroll
        for (int n = 1; n < D_STATE; n++)
            pw[n] = pw[n >> 1] * pw[(n - 1) >> 1];
        const size_t hbase = ((size_t)(b * NC + j) * D_STATE) * D_HALF + d;
#pragma unroll
        for (int n = 0; n < D_STATE; n++)
            h[n] = fmaf(h[n], pw[n], g_hloc[hbase + (size_t)n * D_HALF]);
    }

    const float Dd = Dvec[d];
    const float* ep  = g_e  + (size_t)base_row * D_HALF + d;
    const float* dup = g_du + (size_t)base_row * D_HALF + d;
    const float* up  = g_u  + (size_t)base_row * D_HALF + d;
    float*       yp  = g_cat + (size_t)base_row * D_INNER + d;

#pragma unroll 4
    for (int t = 0; t < CL; t++) {
        float e  = ep [(size_t)t * D_HALF];
        float du = dup[(size_t)t * D_HALF];
        float uu = up [(size_t)t * D_HALF];
        float pw[D_STATE];
        pw[0] = e;
#pragma unroll
        for (int n = 1; n < D_STATE; n++)
            pw[n] = pw[n >> 1] * pw[(n - 1) >> 1];
        float y = 0.f;
#pragma unroll
        for (int n = 0; n < D_STATE; n++) {
            h[n] = fmaf(h[n], pw[n], du * sB[t][n]);
            y    = fmaf(h[n], sC[t][n], y);
        }
        yp[(size_t)t * D_INNER] = f2tff(fmaf(uu, Dd, y));
    }
}

/* ------------------------------------------------------------------ */
extern "C" void kernel_launch(void* const* d_in, const int* in_sizes, int n_in,
                              void* d_out, int out_size)
{
    const float* x        = (const float*)d_in[0];
    const float* W_in     = (const float*)d_in[1];
    const float* conv_x_w = (const float*)d_in[2];
    const float* conv_x_b = (const float*)d_in[3];
    const float* conv_z_w = (const float*)d_in[4];
    const float* conv_z_b = (const float*)d_in[5];
    const float* W_xdbl   = (const float*)d_in[6];
    const float* W_dt     = (const float*)d_in[7];
    const float* inv_dt   = (const float*)d_in[8];
    const float* Dvec     = (const float*)d_in[9];
    const float* W_out    = (const float*)d_in[10];
    const float* b_out    = (const float*)d_in[11];
    float* out = (float*)d_out;

    float *xz, *u, *xdbl, *e, *du, *cat, *x32, *wr;
    cudaGetSymbolAddress((void**)&xz,   g_xz);
    cudaGetSymbolAddress((void**)&u,    g_u);
    cudaGetSymbolAddress((void**)&xdbl, g_xdbl);
    cudaGetSymbolAddress((void**)&e,    g_e);
    cudaGetSymbolAddress((void**)&du,   g_du);
    cudaGetSymbolAddress((void**)&cat,  g_cat);
    cudaGetSymbolAddress((void**)&x32,  g_x32);
    cudaGetSymbolAddress((void**)&wr,   g_wr);

    /* 0. round inputs/weights to tf32 once */
    round_tf32_kernel<<<(ROWS * D_MODEL / 4 + 255) / 256, 256>>>(x, x32, ROWS * D_MODEL / 4);
    round_tf32_kernel<<<(D_MODEL * D_INNER / 4 + 255) / 256, 256>>>(W_in, wr + WR_IN, D_MODEL * D_INNER / 4);
    round_tf32_kernel<<<(D_INNER * D_MODEL / 4 + 255) / 256, 256>>>(W_out, wr + WR_OUT, D_INNER * D_MODEL / 4);
    round_tf32_kernel<<<(D_HALF * XDBL_W / 4 + 255) / 256, 256>>>(W_xdbl, wr + WR_XD, D_HALF * XDBL_W / 4);
    round_tf32_kernel<<<(DT_RANK * D_HALF / 4 + 255) / 256, 256>>>(W_dt, wr + WR_DT, DT_RANK * D_HALF / 4);

    /* 1. xz = x @ W_in : (8192,1024)@(1024,2048) */
    tgemm_kernel<<<dim3(D_INNER / BN, ROWS / BM), 256>>>(
        x32, wr + WR_IN, xz, ROWS, D_INNER, D_MODEL,
        D_MODEL, D_INNER, D_INNER, 0, nullptr, nullptr, nullptr);

    /* 2. depthwise conv + SiLU on both halves */
    conv_silu_kernel<<<(B_SZ * LSEQ * D_INNER) / 256, 256>>>(
        conv_x_w, conv_x_b, conv_z_w, conv_z_b);

    /* 3. x_dbl = u @ W_xdbl : (8192,1024)@(1024,96), tf32-rounded out */
    tgemm_kernel<<<dim3(1, ROWS / BM), 256>>>(
        u, wr + WR_XD, xdbl, ROWS, XDBL_W, D_HALF,
        D_HALF, XDBL_W, XDBL_W, 3, nullptr, nullptr, nullptr);

    /* 4. delta GEMM + fused epilogue -> e = exp(-delta), du = delta*u */
    tgemm_kernel<<<dim3(D_HALF / BN, ROWS / BM), 256>>>(
        xdbl, wr + WR_DT, e, ROWS, D_HALF, DT_RANK,
        XDBL_W, D_HALF, D_HALF, 1, inv_dt, u, du);

    /* 5. parallel selective scan -> y (left half of g_cat) */
    scan_pass1_kernel<<<dim3(D_HALF / 128, NC, B_SZ), 128>>>();
    scan_pass2_kernel<<<dim3(D_HALF / 128, NC, B_SZ), 128>>>(Dvec);

    /* 6. out = [y | z] @ W_out + b_out : (8192,2048)@(2048,1024) */
    tgemm_kernel<<<dim3(D_MODEL / BN, ROWS / BM), 256>>>(
        cat, wr + WR_OUT, out, ROWS, D_MODEL, D_INNER,
        D_INNER, D_MODEL, D_MODEL, 2, b_out, nullptr, nullptr);
}

// round 13
// speedup vs baseline: 3.0399x; 1.0707x over previous
#include <cuda_runtime.h>
#include <math.h>
#include <stdint.h>

#define B_SZ    4
#define LSEQ    2048
#define D_MODEL 1024
#define D_INNER 2048
#define D_HALF  1024
#define D_STATE 16
#define DT_RANK 64
#define ROWS    (B_SZ * LSEQ)   /* 8192 */
#define XDBL_W  96              /* DT_RANK + 2*D_STATE */
#define NC      16              /* scan chunks */
#define CL      128             /* steps per chunk */

/* ------------------------------------------------------------------ */
/* Scratch (allocation-free rule: __device__ globals)                  */
/* ------------------------------------------------------------------ */
__device__ float g_xz   [ROWS * D_INNER];          /* 64 MB */
__device__ float g_u    [ROWS * D_HALF];           /* 32 MB xs (tf32-rounded) */
__device__ float g_xdbl [ROWS * XDBL_W];           /*  3 MB (tf32-rounded)    */
__device__ float g_e    [ROWS * D_HALF];           /* 32 MB exp(-delta)       */
__device__ float g_du   [ROWS * D_HALF];           /* 32 MB delta*u           */
__device__ float g_cat  [ROWS * D_INNER];          /* 64 MB [y | z] rounded   */
__device__ float g_hloc [B_SZ * NC * D_STATE * D_HALF]; /* 4 MB */
__device__ float g_P    [B_SZ * NC * D_HALF];      /* 256 KB */
__device__ float g_x32  [ROWS * D_MODEL];          /* 32 MB tf32-rounded x    */
__device__ float g_wr   [4 * 1024 * 1024 + 98304 + 65536]; /* rounded weights */

#define WR_IN 0
#define WR_OUT (2 * 1024 * 1024)
#define WR_XD  (4 * 1024 * 1024)
#define WR_DT  (4 * 1024 * 1024 + 98304)

__device__ __forceinline__ uint32_t f2tf(float x) {
    uint32_t r;
    asm("cvt.rna.tf32.f32 %0, %1;" : "=r"(r) : "f"(x));
    return r;
}
__device__ __forceinline__ float f2tff(float x) { return __uint_as_float(f2tf(x)); }

__device__ __forceinline__ uint32_t smem_u32(const void* p) {
    return (uint32_t)__cvta_generic_to_shared(p);
}

__device__ __forceinline__ void cpa16(uint32_t dst, const float* src, int sz) {
    asm volatile("cp.async.cg.shared.global [%0], [%1], 16, %2;"
                 :: "r"(dst), "l"(src), "r"(sz));
}
__device__ __forceinline__ void cpa_commit() {
    asm volatile("cp.async.commit_group;");
}
template <int N>
__device__ __forceinline__ void cpa_wait() {
    asm volatile("cp.async.wait_group %0;" :: "n"(N));
}

#define LDSM4(r, addr)                                                     \
    asm volatile("ldmatrix.sync.aligned.m8n8.x4.shared.b16 "               \
                 "{%0,%1,%2,%3}, [%4];"                                    \
                 : "=r"((r)[0]), "=r"((r)[1]), "=r"((r)[2]), "=r"((r)[3])  \
                 : "r"(addr))

__device__ __forceinline__ void mma_tf32(float* c, const uint32_t* a, const uint32_t* b) {
    asm volatile(
        "mma.sync.aligned.m16n8k8.row.col.f32.tf32.tf32.f32 "
        "{%0,%1,%2,%3}, {%4,%5,%6,%7}, {%8,%9}, {%0,%1,%2,%3};"
        : "+f"(c[0]), "+f"(c[1]), "+f"(c[2]), "+f"(c[3])
        : "r"(a[0]), "r"(a[1]), "r"(a[2]), "r"(a[3]), "r"(b[0]), "r"(b[1]));
}

/* ------------------------------------------------------------------ */
/* tf32 round-copy: out[i] = rna_tf32(in[i]), n % 4 == 0               */
/* ------------------------------------------------------------------ */
__global__ __launch_bounds__(256)
void round_tf32_kernel(const float* __restrict__ in, float* __restrict__ out, int n4)
{
    int i = blockIdx.x * blockDim.x + threadIdx.x;
    if (i < n4) {
        float4 v = reinterpret_cast<const float4*>(in)[i];
        v.x = f2tff(v.x); v.y = f2tff(v.y); v.z = f2tff(v.z); v.w = f2tff(v.w);
        reinterpret_cast<float4*>(out)[i] = v;
    }
}

/* ------------------------------------------------------------------ */
/* TF32 GEMM, 3-stage cp.async ring (ONE sync per slab), ldmatrix A.   */
/* Operands MUST be pre-rounded tf32. C = A(MxK) @ B(KxN) row-major.   */
/* mode 0: C=v; 3: C=tf32(v);                                          */
/* mode 1: delta-epilogue: v+=2*bias; C=1/(1+e^v); C2=softplus(v)*U.   */
/* mode 2: C=v+bias[col].                                              */
/* ------------------------------------------------------------------ */
#define BM 128
#define BN 128
#define BK 16
#define SA 20
#define SB 136
#define A_ST_B (BM * SA * 4)   /* 10240 bytes */
#define B_ST_B (BK * SB * 4)   /*  8704 bytes */
#define NSTG 3
#define SMEM_BYTES (NSTG * (A_ST_B + B_ST_B))   /* 56832 */

__global__ __launch_bounds__(256)
void tgemm_kernel(const float* __restrict__ A, const float* __restrict__ B,
                  float* __restrict__ C, int M, int N, int K,
                  int lda, int ldb, int ldc,
                  int mode, const float* __restrict__ bias,
                  const float* __restrict__ U, float* __restrict__ C2)
{
    extern __shared__ float smem[];
    float* AsBase = smem;                       /* NSTG * BM*SA floats */
    float* BsBase = smem + NSTG * BM * SA;      /* NSTG * BK*SB floats */

    const int tid    = threadIdx.x;
    const int lane   = tid & 31;
    const int wid    = tid >> 5;
    const int warp_m = wid & 3;
    const int warp_n = wid >> 2;
    const int block_row = blockIdx.y * BM;
    const int block_col = blockIdx.x * BN;

    float acc[2][8][4];
#pragma unroll
    for (int mt = 0; mt < 2; mt++)
#pragma unroll
        for (int nt = 0; nt < 8; nt++)
#pragma unroll
            for (int i = 0; i < 4; i++) acc[mt][nt][i] = 0.f;

    /* staging mapping */
    const int a_r = tid >> 2;            /* 0..63 */
    const int a_k = (tid & 3) << 2;      /* 0,4,8,12 */
    const int b_r = tid >> 5;            /* 0..7  */
    const int b_c = (tid & 31) << 2;     /* 0..124 */
    const int colg = block_col + b_c;
    const int szb  = (colg < N) ? 16 : 0;
    const int colc = (colg < N) ? colg : 0;

    const float* Ap0 = A + (size_t)(block_row + a_r) * lda + a_k;
    const float* Ap1 = Ap0 + (size_t)64 * lda;
    const float* Bp0 = B + (size_t)b_r * ldb + colc;
    const float* Bp1 = B + (size_t)(b_r + 8) * ldb + colc;

    const uint32_t aD0 = smem_u32(&AsBase[a_r * SA + a_k]);
    const uint32_t aD1 = smem_u32(&AsBase[(a_r + 64) * SA + a_k]);
    const uint32_t bD0 = smem_u32(&BsBase[b_r * SB + b_c]);
    const uint32_t bD1 = smem_u32(&BsBase[(b_r + 8) * SB + b_c]);

    /* ldmatrix per-lane A-fragment base byte offset (R3-proven mapping) */
    const int L = lane;
    const uint32_t a_off =
        ((warp_m * 32 + (L & 7) + ((L >> 3) & 1) * 8) * SA + ((L >> 4) & 1) * 4) * 4;
    const uint32_t as_u32 = smem_u32(AsBase);

    const int nslab = K / BK;

    /* prologue: stage slabs 0 and 1 into stages 0 and 1 */
    {
        cpa16(aD0, Ap0, 16);
        cpa16(aD1, Ap1, 16);
        cpa16(bD0, Bp0, szb);
        cpa16(bD1, Bp1, szb);
        cpa_commit();
        if (nslab > 1) {
            const size_t kob = (size_t)BK * ldb;
            cpa16(aD0 + A_ST_B, Ap0 + BK, 16);
            cpa16(aD1 + A_ST_B, Ap1 + BK, 16);
            cpa16(bD0 + B_ST_B, Bp0 + kob, szb);
            cpa16(bD1 + B_ST_B, Bp1 + kob, szb);
        }
        cpa_commit();
    }

    int st = 0;
    for (int s = 0; s < nslab; s++) {
        cpa_wait<1>();          /* slab s landed (s+1 may still be pending) */
        __syncthreads();        /* also guards stage (st+2)%3 reuse below   */

        if (s + 2 < nslab) {
            int b3 = st + 2; if (b3 >= NSTG) b3 -= NSTG;
            const int ko = (s + 2) * BK;
            const size_t kob = (size_t)ko * ldb;
            cpa16(aD0 + b3 * A_ST_B, Ap0 + ko, 16);
            cpa16(aD1 + b3 * A_ST_B, Ap1 + ko, 16);
            cpa16(bD0 + b3 * B_ST_B, Bp0 + kob, szb);
            cpa16(bD1 + b3 * B_ST_B, Bp1 + kob, szb);
        }
        cpa_commit();           /* uniform one group per iteration */

        const uint32_t ab = as_u32 + st * A_ST_B + a_off;
        const uint32_t* Bsb = reinterpret_cast<const uint32_t*>(BsBase) + st * BK * SB;
#pragma unroll
        for (int ks = 0; ks < 2; ks++) {
            uint32_t af[2][4];
            uint32_t bf[8][2];
            LDSM4(af[0], ab + 0 * (16 * SA * 4) + ks * 32);
            LDSM4(af[1], ab + 1 * (16 * SA * 4) + ks * 32);
            const int coln = warp_n * 64 + (lane >> 2);
#pragma unroll
            for (int nt = 0; nt < 8; nt++) {
                bf[nt][0] = Bsb[(ks * 8 + (lane & 3)) * SB + coln + nt * 8];
                bf[nt][1] = Bsb[(ks * 8 + 4 + (lane & 3)) * SB + coln + nt * 8];
            }
#pragma unroll
            for (int mt = 0; mt < 2; mt++)
#pragma unroll
                for (int nt = 0; nt < 8; nt++)
                    mma_tf32(acc[mt][nt], af[mt], bf[nt]);
        }
        st = st + 1; if (st >= NSTG) st = 0;
    }

#pragma unroll
    for (int mt = 0; mt < 2; mt++) {
        int row = block_row + warp_m * 32 + mt * 16 + (lane >> 2);
#pragma unroll
        for (int nt = 0; nt < 8; nt++) {
            int col = block_col + warp_n * 64 + nt * 8 + (lane & 3) * 2;
            if (col < N) {
#pragma unroll
                for (int half = 0; half < 2; half++) {
                    int r = row + half * 8;
                    float v0 = acc[mt][nt][half * 2 + 0];
                    float v1 = acc[mt][nt][half * 2 + 1];
                    if (mode == 1) {
                        v0 += 2.f * bias[col];
                        v1 += 2.f * bias[col + 1];
                        float t0 = __expf(v0), t1 = __expf(v1);
                        float d0 = (v0 > 20.f) ? v0 : log1pf(t0);
                        float d1 = (v1 > 20.f) ? v1 : log1pf(t1);
                        float e0 = __fdividef(1.f, 1.f + t0);
                        float e1 = __fdividef(1.f, 1.f + t1);
                        float2 uu = *reinterpret_cast<const float2*>(
                            &U[(size_t)r * ldc + col]);
                        *reinterpret_cast<float2*>(&C[(size_t)r * ldc + col]) =
                            make_float2(e0, e1);
                        *reinterpret_cast<float2*>(&C2[(size_t)r * ldc + col]) =
                            make_float2(d0 * uu.x, d1 * uu.y);
                        continue;
                    }
                    if (mode == 2) {
                        v0 += bias[col];
                        v1 += bias[col + 1];
                    } else if (mode == 3) {
                        v0 = f2tff(v0);
                        v1 = f2tff(v1);
                    }
                    *reinterpret_cast<float2*>(&C[(size_t)r * ldc + col]) =
                        make_float2(v0, v1);
                }
            }
        }
    }
}

/* ------------------------------------------------------------------ */
/* Depthwise conv1d (k=4, SAME) + SiLU. Writes tf32-rounded outputs.   */
/* ------------------------------------------------------------------ */
__global__ __launch_bounds__(256)
void conv_silu_kernel(const float* __restrict__ wx, const float* __restrict__ bx,
                      const float* __restrict__ wz, const float* __restrict__ bz)
{
    int idx = blockIdx.x * blockDim.x + threadIdx.x;
    if (idx >= B_SZ * LSEQ * D_INNER) return;
    int c = idx % D_INNER;
    int l = (idx / D_INNER) % LSEQ;
    int b = idx / (D_INNER * LSEQ);

    bool isx = (c < D_HALF);
    int ch = isx ? c : c - D_HALF;
    const float* w = isx ? wx : wz;
    float acc = isx ? bx[ch] : bz[ch];

#pragma unroll
    for (int j = 0; j < 4; j++) {
        int ll = l + j - 1;
        if (ll >= 0 && ll < LSEQ)
            acc = fmaf(w[j * D_HALF + ch],
                       g_xz[((size_t)(b * LSEQ + ll)) * D_INNER + c], acc);
    }
    float s = f2tff(acc / (1.f + __expf(-acc)));

    size_t row = (size_t)(b * LSEQ + l);
    if (isx) g_u[row * D_HALF + ch] = s;
    else     g_cat[row * D_INNER + D_HALF + ch] = s;
}

/* ------------------------------------------------------------------ */
/* Parallel scan pass 1                                                */
/* ------------------------------------------------------------------ */
__global__ __launch_bounds__(128)
void scan_pass1_kernel()
{
    const int tid = threadIdx.x;
    const int b = blockIdx.z, c = blockIdx.y;
    const int d = blockIdx.x * 128 + tid;

    __shared__ float sB[CL][D_STATE];
    const int base_row = b * LSEQ + c * CL;
    for (int i = tid; i < CL * D_STATE; i += 128)
        sB[i >> 4][i & 15] =
            g_xdbl[(size_t)(base_row + (i >> 4)) * XDBL_W + DT_RANK + (i & 15)];
    __syncthreads();

    const float* ep  = g_e  + (size_t)base_row * D_HALF + d;
    const float* dup = g_du + (size_t)base_row * D_HALF + d;

    float h[D_STATE];
#pragma unroll
    for (int n = 0; n < D_STATE; n++) h[n] = 0.f;
    float P = 1.f;

#pragma unroll 4
    for (int t = 0; t < CL; t++) {
        float e  = ep [(size_t)t * D_HALF];
        float du = dup[(size_t)t * D_HALF];
        float pw[D_STATE];
        pw[0] = e;
#pragma unroll
        for (int n = 1; n < D_STATE; n++)
            pw[n] = pw[n >> 1] * pw[(n - 1) >> 1];
#pragma unroll
        for (int n = 0; n < D_STATE; n++)
            h[n] = fmaf(h[n], pw[n], du * sB[t][n]);
        P *= e;
    }

    const size_t hbase = ((size_t)(b * NC + c) * D_STATE) * D_HALF + d;
#pragma unroll
    for (int n = 0; n < D_STATE; n++)
        g_hloc[hbase + (size_t)n * D_HALF] = h[n];
    g_P[(size_t)(b * NC + c) * D_HALF + d] = P;
}

/* ------------------------------------------------------------------ */
/* Parallel scan pass 2 (emits tf32-rounded y)                         */
/* ------------------------------------------------------------------ */
__global__ __launch_bounds__(128)
void scan_pass2_kernel(const float* __restrict__ Dvec)
{
    const int tid = threadIdx.x;
    const int b = blockIdx.z, c = blockIdx.y;
    const int d = blockIdx.x * 128 + tid;

    __shared__ float sB[CL][D_STATE];
    __shared__ float sC[CL][D_STATE];
    const int base_row = b * LSEQ + c * CL;
    for (int i = tid; i < CL * D_STATE; i += 128) {
        size_t src = (size_t)(base_row + (i >> 4)) * XDBL_W + DT_RANK + (i & 15);
        sB[i >> 4][i & 15] = g_xdbl[src];
        sC[i >> 4][i & 15] = g_xdbl[src + D_STATE];
    }
    __syncthreads();

    float h[D_STATE];
#pragma unroll
    for (int n = 0; n < D_STATE; n++) h[n] = 0.f;
    for (int j = 0; j < c; j++) {
        float Pj = g_P[(size_t)(b * NC + j) * D_HALF + d];
        float pw[D_STATE];
        pw[0] = Pj;
#pragma unroll
        for (int n = 1; n < D_STATE; n++)
            pw[n] = pw[n >> 1] * pw[(n - 1) >> 1];
        const size_t hbase = ((size_t)(b * NC + j) * D_STATE) * D_HALF + d;
#pragma unroll
        for (int n = 0; n < D_STATE; n++)
            h[n] = fmaf(h[n], pw[n], g_hloc[hbase + (size_t)n * D_HALF]);
    }

    const float Dd = Dvec[d];
    const float* ep  = g_e  + (size_t)base_row * D_HALF + d;
    const float* dup = g_du + (size_t)base_row * D_HALF + d;
    const float* up  = g_u  + (size_t)base_row * D_HALF + d;
    float*       yp  = g_cat + (size_t)base_row * D_INNER + d;

#pragma unroll 4
    for (int t = 0; t < CL; t++) {
        float e  = ep [(size_t)t * D_HALF];
        float du = dup[(size_t)t * D_HALF];
        float uu = up [(size_t)t * D_HALF];
        float pw[D_STATE];
        pw[0] = e;
#pragma unroll
        for (int n = 1; n < D_STATE; n++)
            pw[n] = pw[n >> 1] * pw[(n - 1) >> 1];
        float y = 0.f;
#pragma unroll
        for (int n = 0; n < D_STATE; n++) {
            h[n] = fmaf(h[n], pw[n], du * sB[t][n]);
            y    = fmaf(h[n], sC[t][n], y);
        }
        yp[(size_t)t * D_INNER] = f2tff(fmaf(uu, Dd, y));
    }
}

/* ------------------------------------------------------------------ */
extern "C" void kernel_launch(void* const* d_in, const int* in_sizes, int n_in,
                              void* d_out, int out_size)
{
    const float* x        = (const float*)d_in[0];
    const float* W_in     = (const float*)d_in[1];
    const float* conv_x_w = (const float*)d_in[2];
    const float* conv_x_b = (const float*)d_in[3];
    const float* conv_z_w = (const float*)d_in[4];
    const float* conv_z_b = (const float*)d_in[5];
    const float* W_xdbl   = (const float*)d_in[6];
    const float* W_dt     = (const float*)d_in[7];
    const float* inv_dt   = (const float*)d_in[8];
    const float* Dvec     = (const float*)d_in[9];
    const float* W_out    = (const float*)d_in[10];
    const float* b_out    = (const float*)d_in[11];
    float* out = (float*)d_out;

    float *xz, *u, *xdbl, *e, *du, *cat, *x32, *wr;
    cudaGetSymbolAddress((void**)&xz,   g_xz);
    cudaGetSymbolAddress((void**)&u,    g_u);
    cudaGetSymbolAddress((void**)&xdbl, g_xdbl);
    cudaGetSymbolAddress((void**)&e,    g_e);
    cudaGetSymbolAddress((void**)&du,   g_du);
    cudaGetSymbolAddress((void**)&cat,  g_cat);
    cudaGetSymbolAddress((void**)&x32,  g_x32);
    cudaGetSymbolAddress((void**)&wr,   g_wr);

    static bool attr_done = false;
    if (!attr_done) {
        cudaFuncSetAttribute(tgemm_kernel,
                             cudaFuncAttributeMaxDynamicSharedMemorySize, SMEM_BYTES);
        attr_done = true;
    }

    /* 0. round inputs/weights to tf32 once */
    round_tf32_kernel<<<(ROWS * D_MODEL / 4 + 255) / 256, 256>>>(x, x32, ROWS * D_MODEL / 4);
    round_tf32_kernel<<<(D_MODEL * D_INNER / 4 + 255) / 256, 256>>>(W_in, wr + WR_IN, D_MODEL * D_INNER / 4);
    round_tf32_kernel<<<(D_INNER * D_MODEL / 4 + 255) / 256, 256>>>(W_out, wr + WR_OUT, D_INNER * D_MODEL / 4);
    round_tf32_kernel<<<(D_HALF * XDBL_W / 4 + 255) / 256, 256>>>(W_xdbl, wr + WR_XD, D_HALF * XDBL_W / 4);
    round_tf32_kernel<<<(DT_RANK * D_HALF / 4 + 255) / 256, 256>>>(W_dt, wr + WR_DT, DT_RANK * D_HALF / 4);

    /* 1. xz = x @ W_in : (8192,1024)@(1024,2048) */
    tgemm_kernel<<<dim3(D_INNER / BN, ROWS / BM), 256, SMEM_BYTES>>>(
        x32, wr + WR_IN, xz, ROWS, D_INNER, D_MODEL,
        D_MODEL, D_INNER, D_INNER, 0, nullptr, nullptr, nullptr);

    /* 2. depthwise conv + SiLU on both halves */
    conv_silu_kernel<<<(B_SZ * LSEQ * D_INNER) / 256, 256>>>(
        conv_x_w, conv_x_b, conv_z_w, conv_z_b);

    /* 3. x_dbl = u @ W_xdbl : (8192,1024)@(1024,96), tf32-rounded out */
    tgemm_kernel<<<dim3(1, ROWS / BM), 256, SMEM_BYTES>>>(
        u, wr + WR_XD, xdbl, ROWS, XDBL_W, D_HALF,
        D_HALF, XDBL_W, XDBL_W, 3, nullptr, nullptr, nullptr);

    /* 4. delta GEMM + fused epilogue -> e = exp(-delta), du = delta*u */
    tgemm_kernel<<<dim3(D_HALF / BN, ROWS / BM), 256, SMEM_BYTES>>>(
        xdbl, wr + WR_DT, e, ROWS, D_HALF, DT_RANK,
        XDBL_W, D_HALF, D_HALF, 1, inv_dt, u, du);

    /* 5. parallel selective scan -> y (left half of g_cat) */
    scan_pass1_kernel<<<dim3(D_HALF / 128, NC, B_SZ), 128>>>();
    scan_pass2_kernel<<<dim3(D_HALF / 128, NC, B_SZ), 128>>>(Dvec);

    /* 6. out = [y | z] @ W_out + b_out : (8192,2048)@(2048,1024) */
    tgemm_kernel<<<dim3(D_MODEL / BN, ROWS / BM), 256, SMEM_BYTES>>>(
        cat, wr + WR_OUT, out, ROWS, D_MODEL, D_INNER,
        D_INNER, D_MODEL, D_MODEL, 2, b_out, nullptr, nullptr);
}

// round 15
// speedup vs baseline: 3.0743x; 1.0113x over previous
#include <cuda_runtime.h>
#include <math.h>
#include <stdint.h>

#define B_SZ    4
#define LSEQ    2048
#define D_MODEL 1024
#define D_INNER 2048
#define D_HALF  1024
#define D_STATE 16
#define DT_RANK 64
#define ROWS    (B_SZ * LSEQ)   /* 8192 */
#define XDBL_W  96              /* DT_RANK + 2*D_STATE */
#define NC      16              /* scan chunks */
#define CL      128             /* steps per chunk */

/* ------------------------------------------------------------------ */
/* Scratch (allocation-free rule: __device__ globals)                  */
/* ------------------------------------------------------------------ */
__device__ float g_xz   [ROWS * D_INNER];
__device__ float g_u    [ROWS * D_HALF];
__device__ float g_xdbl [ROWS * XDBL_W];
__device__ float g_e    [ROWS * D_HALF];
__device__ float g_du   [ROWS * D_HALF];
__device__ float g_cat  [ROWS * D_INNER];
__device__ float g_hloc [B_SZ * NC * D_STATE * D_HALF];
__device__ float g_P    [B_SZ * NC * D_HALF];
__device__ float g_x32  [ROWS * D_MODEL];
__device__ float g_wr   [4 * 1024 * 1024 + 98304 + 65536];

#define WR_IN 0
#define WR_OUT (2 * 1024 * 1024)
#define WR_XD  (4 * 1024 * 1024)
#define WR_DT  (4 * 1024 * 1024 + 98304)

__device__ __forceinline__ uint32_t f2tf(float x) {
    uint32_t r;
    asm("cvt.rna.tf32.f32 %0, %1;" : "=r"(r) : "f"(x));
    return r;
}
__device__ __forceinline__ float f2tff(float x) { return __uint_as_float(f2tf(x)); }

__device__ __forceinline__ uint32_t smem_u32(const void* p) {
    return (uint32_t)__cvta_generic_to_shared(p);
}

__device__ __forceinline__ void cpa16(uint32_t dst, const float* src, int sz) {
    asm volatile("cp.async.cg.shared.global [%0], [%1], 16, %2;"
                 :: "r"(dst), "l"(src), "r"(sz));
}
__device__ __forceinline__ void cpa_commit() {
    asm volatile("cp.async.commit_group;");
}
template <int N>
__device__ __forceinline__ void cpa_wait() {
    asm volatile("cp.async.wait_group %0;" :: "n"(N));
}

#define LDSM4(r, addr)                                                     \
    asm volatile("ldmatrix.sync.aligned.m8n8.x4.shared.b16 "               \
                 "{%0,%1,%2,%3}, [%4];"                                    \
                 : "=r"((r)[0]), "=r"((r)[1]), "=r"((r)[2]), "=r"((r)[3])  \
                 : "r"(addr))

__device__ __forceinline__ void mma_tf32(float* c, const uint32_t* a, const uint32_t* b) {
    asm volatile(
        "mma.sync.aligned.m16n8k8.row.col.f32.tf32.tf32.f32 "
        "{%0,%1,%2,%3}, {%4,%5,%6,%7}, {%8,%9}, {%0,%1,%2,%3};"
        : "+f"(c[0]), "+f"(c[1]), "+f"(c[2]), "+f"(c[3])
        : "r"(a[0]), "r"(a[1]), "r"(a[2]), "r"(a[3]), "r"(b[0]), "r"(b[1]));
}

/* ------------------------------------------------------------------ */
__global__ __launch_bounds__(256)
void round_tf32_kernel(const float* __restrict__ in, float* __restrict__ out, int n4)
{
    int i = blockIdx.x * blockDim.x + threadIdx.x;
    if (i < n4) {
        float4 v = reinterpret_cast<const float4*>(in)[i];
        v.x = f2tff(v.x); v.y = f2tff(v.y); v.z = f2tff(v.z); v.w = f2tff(v.w);
        reinterpret_cast<float4*>(out)[i] = v;
    }
}

/* ------------------------------------------------------------------ */
/* TF32 GEMM, 3-stage cp.async ring, ldmatrix A, coalesced smem epi.   */
/* Operands pre-rounded tf32. C = A(MxK) @ B(KxN) row-major.           */
/* mode 0: C=v; 3: C=tf32(v); 2: C=v+bias[col];                        */
/* mode 1: v+=2*bias; C=1/(1+e^v); C2=softplus(v)*U.                   */
/* ------------------------------------------------------------------ */
#define BM 128
#define BN 128
#define BK 16
#define SA 20
#define SB 136
#define A_ST_B (BM * SA * 4)   /* 10240 bytes */
#define B_ST_B (BK * SB * 4)   /*  8704 bytes */
#define NSTG 3
#define SMEM_BYTES (NSTG * (A_ST_B + B_ST_B))   /* 56832 */
#define EROW 132               /* epilogue smem row stride (floats) */

__global__ __launch_bounds__(256)
void tgemm_kernel(const float* __restrict__ A, const float* __restrict__ B,
                  float* __restrict__ C, int M, int N, int K,
                  int lda, int ldb, int ldc,
                  int mode, const float* __restrict__ bias,
                  const float* __restrict__ U, float* __restrict__ C2)
{
    extern __shared__ float smem[];
    float* AsBase = smem;
    float* BsBase = smem + NSTG * BM * SA;

    const int tid    = threadIdx.x;
    const int lane   = tid & 31;
    const int wid    = tid >> 5;
    const int warp_m = wid & 3;
    const int warp_n = wid >> 2;
    const int block_row = blockIdx.y * BM;
    const int block_col = blockIdx.x * BN;

    float acc[2][8][4];
#pragma unroll
    for (int mt = 0; mt < 2; mt++)
#pragma unroll
        for (int nt = 0; nt < 8; nt++)
#pragma unroll
            for (int i = 0; i < 4; i++) acc[mt][nt][i] = 0.f;

    const int a_r = tid >> 2;
    const int a_k = (tid & 3) << 2;
    const int b_r = tid >> 5;
    const int b_c = (tid & 31) << 2;
    const int colg = block_col + b_c;
    const int szb  = (colg < N) ? 16 : 0;
    const int colc = (colg < N) ? colg : 0;

    const float* Ap0 = A + (size_t)(block_row + a_r) * lda + a_k;
    const float* Ap1 = Ap0 + (size_t)64 * lda;
    const float* Bp0 = B + (size_t)b_r * ldb + colc;
    const float* Bp1 = B + (size_t)(b_r + 8) * ldb + colc;

    const uint32_t aD0 = smem_u32(&AsBase[a_r * SA + a_k]);
    const uint32_t aD1 = smem_u32(&AsBase[(a_r + 64) * SA + a_k]);
    const uint32_t bD0 = smem_u32(&BsBase[b_r * SB + b_c]);
    const uint32_t bD1 = smem_u32(&BsBase[(b_r + 8) * SB + b_c]);

    const int L = lane;
    const uint32_t a_off =
        ((warp_m * 32 + (L & 7) + ((L >> 3) & 1) * 8) * SA + ((L >> 4) & 1) * 4) * 4;
    const uint32_t as_u32 = smem_u32(AsBase);

    const int nslab = K / BK;

    {
        cpa16(aD0, Ap0, 16);
        cpa16(aD1, Ap1, 16);
        cpa16(bD0, Bp0, szb);
        cpa16(bD1, Bp1, szb);
        cpa_commit();
        if (nslab > 1) {
            const size_t kob = (size_t)BK * ldb;
            cpa16(aD0 + A_ST_B, Ap0 + BK, 16);
            cpa16(aD1 + A_ST_B, Ap1 + BK, 16);
            cpa16(bD0 + B_ST_B, Bp0 + kob, szb);
            cpa16(bD1 + B_ST_B, Bp1 + kob, szb);
        }
        cpa_commit();
    }

    int st = 0;
    for (int s = 0; s < nslab; s++) {
        cpa_wait<1>();
        __syncthreads();

        if (s + 2 < nslab) {
            int b3 = st + 2; if (b3 >= NSTG) b3 -= NSTG;
            const int ko = (s + 2) * BK;
            const size_t kob = (size_t)ko * ldb;
            cpa16(aD0 + b3 * A_ST_B, Ap0 + ko, 16);
            cpa16(aD1 + b3 * A_ST_B, Ap1 + ko, 16);
            cpa16(bD0 + b3 * B_ST_B, Bp0 + kob, szb);
            cpa16(bD1 + b3 * B_ST_B, Bp1 + kob, szb);
        }
        cpa_commit();

        const uint32_t ab = as_u32 + st * A_ST_B + a_off;
        const uint32_t* Bsb = reinterpret_cast<const uint32_t*>(BsBase) + st * BK * SB;
#pragma unroll
        for (int ks = 0; ks < 2; ks++) {
            uint32_t af[2][4];
            uint32_t bf[8][2];
            LDSM4(af[0], ab + 0 * (16 * SA * 4) + ks * 32);
            LDSM4(af[1], ab + 1 * (16 * SA * 4) + ks * 32);
            const int coln = warp_n * 64 + (lane >> 2);
#pragma unroll
            for (int nt = 0; nt < 8; nt++) {
                bf[nt][0] = Bsb[(ks * 8 + (lane & 3)) * SB + coln + nt * 8];
                bf[nt][1] = Bsb[(ks * 8 + 4 + (lane & 3)) * SB + coln + nt * 8];
            }
#pragma unroll
            for (int mt = 0; mt < 2; mt++)
#pragma unroll
                for (int nt = 0; nt < 8; nt++)
                    mma_tf32(acc[mt][nt], af[mt], bf[nt]);
        }
        st = st + 1; if (st >= NSTG) st = 0;
    }

    /* ---- coalesced epilogue through smem (raw v staged, transform on
       write). Per mt: CTA holds 64 distinct rows x 128 cols. ---- */
    __syncthreads();   /* mainloop smem reads done before overwrite */
#pragma unroll
    for (int mt = 0; mt < 2; mt++) {
        /* store phase: raw accumulators -> smem */
#pragma unroll
        for (int nt = 0; nt < 8; nt++) {
#pragma unroll
            for (int half = 0; half < 2; half++) {
                int srow = warp_m * 16 + (lane >> 2) + half * 8;
                int scol = warp_n * 64 + nt * 8 + (lane & 3) * 2;
                *reinterpret_cast<float2*>(&smem[srow * EROW + scol]) =
                    make_float2(acc[mt][nt][half * 2 + 0],
                                acc[mt][nt][half * 2 + 1]);
            }
        }
        __syncthreads();

        /* write phase: coalesced float4 rows, mode transform applied */
#pragma unroll
        for (int it = 0; it < 8; it++) {
            int idx = it * 256 + tid;       /* 0..2047 */
            int srow = idx >> 5;            /* 0..63  */
            int c4   = idx & 31;            /* 0..31  */
            int gcol = block_col + c4 * 4;
            if (gcol < N) {
                int grow = block_row + (srow >> 4) * 32 + mt * 16 + (srow & 15);
                float4 v = *reinterpret_cast<const float4*>(&smem[srow * EROW + c4 * 4]);
                if (mode == 1) {
                    float4 bi = *reinterpret_cast<const float4*>(&bias[gcol]);
                    v.x += 2.f * bi.x; v.y += 2.f * bi.y;
                    v.z += 2.f * bi.z; v.w += 2.f * bi.w;
                    float t0 = __expf(v.x), t1 = __expf(v.y);
                    float t2 = __expf(v.z), t3 = __expf(v.w);
                    float4 dd;
                    dd.x = (v.x > 20.f) ? v.x : log1pf(t0);
                    dd.y = (v.y > 20.f) ? v.y : log1pf(t1);
                    dd.z = (v.z > 20.f) ? v.z : log1pf(t2);
                    dd.w = (v.w > 20.f) ? v.w : log1pf(t3);
                    float4 ee;
                    ee.x = __fdividef(1.f, 1.f + t0);
                    ee.y = __fdividef(1.f, 1.f + t1);
                    ee.z = __fdividef(1.f, 1.f + t2);
                    ee.w = __fdividef(1.f, 1.f + t3);
                    float4 uu = *reinterpret_cast<const float4*>(
                        &U[(size_t)grow * ldc + gcol]);
                    dd.x *= uu.x; dd.y *= uu.y; dd.z *= uu.z; dd.w *= uu.w;
                    *reinterpret_cast<float4*>(&C [(size_t)grow * ldc + gcol]) = ee;
                    *reinterpret_cast<float4*>(&C2[(size_t)grow * ldc + gcol]) = dd;
                } else {
                    if (mode == 2) {
                        float4 bi = *reinterpret_cast<const float4*>(&bias[gcol]);
                        v.x += bi.x; v.y += bi.y; v.z += bi.z; v.w += bi.w;
                    } else if (mode == 3) {
                        v.x = f2tff(v.x); v.y = f2tff(v.y);
                        v.z = f2tff(v.z); v.w = f2tff(v.w);
                    }
                    *reinterpret_cast<float4*>(&C[(size_t)grow * ldc + gcol]) = v;
                }
            }
        }
        __syncthreads();
    }
}

/* ------------------------------------------------------------------ */
/* BM=64 GEMM variant (for the N=96 x_dbl GEMM: 2x CTA parallelism).   */
/* mode 3 epilogue (tf32 round), direct stores, N guard.               */
/* ------------------------------------------------------------------ */
#define A64_ST_B (64 * SA * 4)   /* 5120 bytes */
#define SMEM64_BYTES (NSTG * (A64_ST_B + B_ST_B))   /* 41472 */

__global__ __launch_bounds__(256)
void tgemm64_kernel(const float* __restrict__ A, const float* __restrict__ B,
                    float* __restrict__ C, int M, int N, int K,
                    int lda, int ldb, int ldc)
{
    extern __shared__ float smem[];
    float* AsBase = smem;
    float* BsBase = smem + NSTG * 64 * SA;

    const int tid    = threadIdx.x;
    const int lane   = tid & 31;
    const int wid    = tid >> 5;
    const int warp_m = wid & 1;          /* 0..1 -> 32-row strip */
    const int warp_n = wid >> 1;         /* 0..3 -> 32-col strip */
    const int block_row = blockIdx.y * 64;
    const int block_col = blockIdx.x * BN;

    float acc[2][4][4];
#pragma unroll
    for (int mt = 0; mt < 2; mt++)
#pragma unroll
        for (int nt = 0; nt < 4; nt++)
#pragma unroll
            for (int i = 0; i < 4; i++) acc[mt][nt][i] = 0.f;

    const int a_r = tid >> 2;            /* 0..63 */
    const int a_k = (tid & 3) << 2;
    const int b_r = tid >> 5;
    const int b_c = (tid & 31) << 2;
    const int colg = block_col + b_c;
    const int szb  = (colg < N) ? 16 : 0;
    const int colc = (colg < N) ? colg : 0;

    const float* Ap0 = A + (size_t)(block_row + a_r) * lda + a_k;
    const float* Bp0 = B + (size_t)b_r * ldb + colc;
    const float* Bp1 = B + (size_t)(b_r + 8) * ldb + colc;

    const uint32_t aD0 = smem_u32(&AsBase[a_r * SA + a_k]);
    const uint32_t bD0 = smem_u32(&BsBase[b_r * SB + b_c]);
    const uint32_t bD1 = smem_u32(&BsBase[(b_r + 8) * SB + b_c]);

    const int L = lane;
    const uint32_t a_off =
        ((warp_m * 32 + (L & 7) + ((L >> 3) & 1) * 8) * SA + ((L >> 4) & 1) * 4) * 4;
    const uint32_t as_u32 = smem_u32(AsBase);

    const int nslab = K / BK;

    {
        cpa16(aD0, Ap0, 16);
        cpa16(bD0, Bp0, szb);
        cpa16(bD1, Bp1, szb);
        cpa_commit();
        if (nslab > 1) {
            const size_t kob = (size_t)BK * ldb;
            cpa16(aD0 + A64_ST_B, Ap0 + BK, 16);
            cpa16(bD0 + B_ST_B, Bp0 + kob, szb);
            cpa16(bD1 + B_ST_B, Bp1 + kob, szb);
        }
        cpa_commit();
    }

    int st = 0;
    for (int s = 0; s < nslab; s++) {
        cpa_wait<1>();
        __syncthreads();

        if (s + 2 < nslab) {
            int b3 = st + 2; if (b3 >= NSTG) b3 -= NSTG;
            const int ko = (s + 2) * BK;
            const size_t kob = (size_t)ko * ldb;
            cpa16(aD0 + b3 * A64_ST_B, Ap0 + ko, 16);
            cpa16(bD0 + b3 * B_ST_B, Bp0 + kob, szb);
            cpa16(bD1 + b3 * B_ST_B, Bp1 + kob, szb);
        }
        cpa_commit();

        const uint32_t ab = as_u32 + st * A64_ST_B + a_off;
        const uint32_t* Bsb = reinterpret_cast<const uint32_t*>(BsBase) + st * BK * SB;
#pragma unroll
        for (int ks = 0; ks < 2; ks++) {
            uint32_t af[2][4];
            uint32_t bf[4][2];
            LDSM4(af[0], ab + 0 * (16 * SA * 4) + ks * 32);
            LDSM4(af[1], ab + 1 * (16 * SA * 4) + ks * 32);
            const int coln = warp_n * 32 + (lane >> 2);
#pragma unroll
            for (int nt = 0; nt < 4; nt++) {
                bf[nt][0] = Bsb[(ks * 8 + (lane & 3)) * SB + coln + nt * 8];
                bf[nt][1] = Bsb[(ks * 8 + 4 + (lane & 3)) * SB + coln + nt * 8];
            }
#pragma unroll
            for (int mt = 0; mt < 2; mt++)
#pragma unroll
                for (int nt = 0; nt < 4; nt++)
                    mma_tf32(acc[mt][nt], af[mt], bf[nt]);
        }
        st = st + 1; if (st >= NSTG) st = 0;
    }

#pragma unroll
    for (int mt = 0; mt < 2; mt++) {
        int row = block_row + warp_m * 32 + mt * 16 + (lane >> 2);
#pragma unroll
        for (int nt = 0; nt < 4; nt++) {
            int col = block_col + warp_n * 32 + nt * 8 + (lane & 3) * 2;
            if (col < N) {
#pragma unroll
                for (int half = 0; half < 2; half++) {
                    int r = row + half * 8;
                    float v0 = f2tff(acc[mt][nt][half * 2 + 0]);
                    float v1 = f2tff(acc[mt][nt][half * 2 + 1]);
                    *reinterpret_cast<float2*>(&C[(size_t)r * ldc + col]) =
                        make_float2(v0, v1);
                }
            }
        }
    }
}

/* ------------------------------------------------------------------ */
/* Depthwise conv1d (k=4, SAME) + SiLU, float2 vectorized.             */
/* ------------------------------------------------------------------ */
__global__ __launch_bounds__(256)
void conv_silu_kernel(const float* __restrict__ wx, const float* __restrict__ bx,
                      const float* __restrict__ wz, const float* __restrict__ bz)
{
    int idx = blockIdx.x * blockDim.x + threadIdx.x;
    const int HW = D_INNER / 2;
    if (idx >= B_SZ * LSEQ * HW) return;
    int c = (idx % HW) * 2;
    int l = (idx / HW) % LSEQ;
    int b = idx / (HW * LSEQ);

    bool isx = (c < D_HALF);
    int ch = isx ? c : c - D_HALF;
    const float* w = isx ? wx : wz;
    const float* bb = isx ? bx : bz;
    float2 acc = *reinterpret_cast<const float2*>(&bb[ch]);

#pragma unroll
    for (int j = 0; j < 4; j++) {
        int ll = l + j - 1;
        if (ll >= 0 && ll < LSEQ) {
            float2 wv = *reinterpret_cast<const float2*>(&w[j * D_HALF + ch]);
            float2 xv = *reinterpret_cast<const float2*>(
                &g_xz[((size_t)(b * LSEQ + ll)) * D_INNER + c]);
            acc.x = fmaf(wv.x, xv.x, acc.x);
            acc.y = fmaf(wv.y, xv.y, acc.y);
        }
    }
    float2 s;
    s.x = f2tff(acc.x / (1.f + __expf(-acc.x)));
    s.y = f2tff(acc.y / (1.f + __expf(-acc.y)));

    size_t row = (size_t)(b * LSEQ + l);
    if (isx) *reinterpret_cast<float2*>(&g_u[row * D_HALF + ch]) = s;
    else     *reinterpret_cast<float2*>(&g_cat[row * D_INNER + D_HALF + ch]) = s;
}

/* ------------------------------------------------------------------ */
/* Parallel scan pass 1                                                */
/* ------------------------------------------------------------------ */
__global__ __launch_bounds__(128)
void scan_pass1_kernel()
{
    const int tid = threadIdx.x;
    const int b = blockIdx.z, c = blockIdx.y;
    const int d = blockIdx.x * 128 + tid;

    __shared__ float sB[CL][D_STATE];
    const int base_row = b * LSEQ + c * CL;
    for (int i = tid; i < CL * D_STATE; i += 128)
        sB[i >> 4][i & 15] =
            g_xdbl[(size_t)(base_row + (i >> 4)) * XDBL_W + DT_RANK + (i & 15)];
    __syncthreads();

    const float* ep  = g_e  + (size_t)base_row * D_HALF + d;
    const float* dup = g_du + (size_t)base_row * D_HALF + d;

    float h[D_STATE];
#pragma unroll
    for (int n = 0; n < D_STATE; n++) h[n] = 0.f;
    float P = 1.f;

#pragma unroll 4
    for (int t = 0; t < CL; t++) {
        float e  = ep [(size_t)t * D_HALF];
        float du = dup[(size_t)t * D_HALF];
        float pw[D_STATE];
        pw[0] = e;
#pragma unroll
        for (int n = 1; n < D_STATE; n++)
            pw[n] = pw[n >> 1] * pw[(n - 1) >> 1];
#pragma unroll
        for (int n = 0; n < D_STATE; n++)
            h[n] = fmaf(h[n], pw[n], du * sB[t][n]);
        P *= e;
    }

    const size_t hbase = ((size_t)(b * NC + c) * D_STATE) * D_HALF + d;
#pragma unroll
    for (int n = 0; n < D_STATE; n++)
        g_hloc[hbase + (size_t)n * D_HALF] = h[n];
    g_P[(size_t)(b * NC + c) * D_HALF + d] = P;
}

/* ------------------------------------------------------------------ */
/* Parallel scan pass 2 (emits tf32-rounded y)                         */
/* ------------------------------------------------------------------ */
__global__ __launch_bounds__(128)
void scan_pass2_kernel(const float* __restrict__ Dvec)
{
    const int tid = threadIdx.x;
    const int b = blockIdx.z, c = blockIdx.y;
    const int d = blockIdx.x * 128 + tid;

    __shared__ float sB[CL][D_STATE];
    __shared__ float sC[CL][D_STATE];
    const int base_row = b * LSEQ + c * CL;
    for (int i = tid; i < CL * D_STATE; i += 128) {
        size_t src = (size_t)(base_row + (i >> 4)) * XDBL_W + DT_RANK + (i & 15);
        sB[i >> 4][i & 15] = g_xdbl[src];
        sC[i >> 4][i & 15] = g_xdbl[src + D_STATE];
    }
    __syncthreads();

    float h[D_STATE];
#pragma unroll
    for (int n = 0; n < D_STATE; n++) h[n] = 0.f;
    for (int j = 0; j < c; j++) {
        float Pj = g_P[(size_t)(b * NC + j) * D_HALF + d];
        float pw[D_STATE];
        pw[0] = Pj;
#pragma unroll
        for (int n = 1; n < D_STATE; n++)
            pw[n] = pw[n >> 1] * pw[(n - 1) >> 1];
        const size_t hbase = ((size_t)(b * NC + j) * D_STATE) * D_HALF + d;
#pragma unroll
        for (int n = 0; n < D_STATE; n++)
            h[n] = fmaf(h[n], pw[n], g_hloc[hbase + (size_t)n * D_HALF]);
    }

    const float Dd = Dvec[d];
    const float* ep  = g_e  + (size_t)base_row * D_HALF + d;
    const float* dup = g_du + (size_t)base_row * D_HALF + d;
    const float* up  = g_u  + (size_t)base_row * D_HALF + d;
    float*       yp  = g_cat + (size_t)base_row * D_INNER + d;

#pragma unroll 4
    for (int t = 0; t < CL; t++) {
        float e  = ep [(size_t)t * D_HALF];
        float du = dup[(size_t)t * D_HALF];
        float uu = up [(size_t)t * D_HALF];
        float pw[D_STATE];
        pw[0] = e;
#pragma unroll
        for (int n = 1; n < D_STATE; n++)
            pw[n] = pw[n >> 1] * pw[(n - 1) >> 1];
        float y = 0.f;
#pragma unroll
        for (int n = 0; n < D_STATE; n++) {
            h[n] = fmaf(h[n], pw[n], du * sB[t][n]);
            y    = fmaf(h[n], sC[t][n], y);
        }
        yp[(size_t)t * D_INNER] = f2tff(fmaf(uu, Dd, y));
    }
}

/* ------------------------------------------------------------------ */
extern "C" void kernel_launch(void* const* d_in, const int* in_sizes, int n_in,
                              void* d_out, int out_size)
{
    const float* x        = (const float*)d_in[0];
    const float* W_in     = (const float*)d_in[1];
    const float* conv_x_w = (const float*)d_in[2];
    const float* conv_x_b = (const float*)d_in[3];
    const float* conv_z_w = (const float*)d_in[4];
    const float* conv_z_b = (const float*)d_in[5];
    const float* W_xdbl   = (const float*)d_in[6];
    const float* W_dt     = (const float*)d_in[7];
    const float* inv_dt   = (const float*)d_in[8];
    const float* Dvec     = (const float*)d_in[9];
    const float* W_out    = (const float*)d_in[10];
    const float* b_out    = (const float*)d_in[11];
    float* out = (float*)d_out;

    float *xz, *u, *xdbl, *e, *du, *cat, *x32, *wr;
    cudaGetSymbolAddress((void**)&xz,   g_xz);
    cudaGetSymbolAddress((void**)&u,    g_u);
    cudaGetSymbolAddress((void**)&xdbl, g_xdbl);
    cudaGetSymbolAddress((void**)&e,    g_e);
    cudaGetSymbolAddress((void**)&du,   g_du);
    cudaGetSymbolAddress((void**)&cat,  g_cat);
    cudaGetSymbolAddress((void**)&x32,  g_x32);
    cudaGetSymbolAddress((void**)&wr,   g_wr);

    static bool attr_done = false;
    if (!attr_done) {
        cudaFuncSetAttribute(tgemm_kernel,
                             cudaFuncAttributeMaxDynamicSharedMemorySize, SMEM_BYTES);
        cudaFuncSetAttribute(tgemm64_kernel,
                             cudaFuncAttributeMaxDynamicSharedMemorySize, SMEM64_BYTES);
        attr_done = true;
    }

    /* 0. round inputs/weights to tf32 once */
    round_tf32_kernel<<<(ROWS * D_MODEL / 4 + 255) / 256, 256>>>(x, x32, ROWS * D_MODEL / 4);
    round_tf32_kernel<<<(D_MODEL * D_INNER / 4 + 255) / 256, 256>>>(W_in, wr + WR_IN, D_MODEL * D_INNER / 4);
    round_tf32_kernel<<<(D_INNER * D_MODEL / 4 + 255) / 256, 256>>>(W_out, wr + WR_OUT, D_INNER * D_MODEL / 4);
    round_tf32_kernel<<<(D_HALF * XDBL_W / 4 + 255) / 256, 256>>>(W_xdbl, wr + WR_XD, D_HALF * XDBL_W / 4);
    round_tf32_kernel<<<(DT_RANK * D_HALF / 4 + 255) / 256, 256>>>(W_dt, wr + WR_DT, DT_RANK * D_HALF / 4);

    /* 1. xz = x @ W_in : (8192,1024)@(1024,2048) */
    tgemm_kernel<<<dim3(D_INNER / BN, ROWS / BM), 256, SMEM_BYTES>>>(
        x32, wr + WR_IN, xz, ROWS, D_INNER, D_MODEL,
        D_MODEL, D_INNER, D_INNER, 0, nullptr, nullptr, nullptr);

    /* 2. depthwise conv + SiLU on both halves */
    conv_silu_kernel<<<(B_SZ * LSEQ * D_INNER / 2) / 256, 256>>>(
        conv_x_w, conv_x_b, conv_z_w, conv_z_b);

    /* 3. x_dbl = u @ W_xdbl : (8192,1024)@(1024,96), BM=64 variant */
    tgemm64_kernel<<<dim3(1, ROWS / 64), 256, SMEM64_BYTES>>>(
        u, wr + WR_XD, xdbl, ROWS, XDBL_W, D_HALF,
        D_HALF, XDBL_W, XDBL_W);

    /* 4. delta GEMM + fused epilogue -> e = exp(-delta), du = delta*u */
    tgemm_kernel<<<dim3(D_HALF / BN, ROWS / BM), 256, SMEM_BYTES>>>(
        xdbl, wr + WR_DT, e, ROWS, D_HALF, DT_RANK,
        XDBL_W, D_HALF, D_HALF, 1, inv_dt, u, du);

    /* 5. parallel selective scan -> y (left half of g_cat) */
    scan_pass1_kernel<<<dim3(D_HALF / 128, NC, B_SZ), 128>>>();
    scan_pass2_kernel<<<dim3(D_HALF / 128, NC, B_SZ), 128>>>(Dvec);

    /* 6. out = [y | z] @ W_out + b_out : (8192,2048)@(2048,1024) */
    tgemm_kernel<<<dim3(D_MODEL / BN, ROWS / BM), 256, SMEM_BYTES>>>(
        cat, wr + WR_OUT, out, ROWS, D_MODEL, D_INNER,
        D_INNER, D_MODEL, D_MODEL, 2, b_out, nullptr, nullptr);
}